// round 12
// baseline (speedup 1.0000x reference)
#include <cuda_runtime.h>

#define NN 325
#define CNN (32*NN)
#define NT 704          // 2 threads per node slot for phases 1/2/5

typedef unsigned long long ull;

static __device__ float g_X0[64*13*CNN];
static __device__ float g_X1[64*13*CNN];
static __device__ float g_skip[64*256*NN];
#define SCT (328*328)
static __device__ float g_sc[832u*SCT];   // per-(b,t) score scratch, L2-resident working set

// ---- MUFU helpers (SFU pipe; rel err ~1e-6) ---------------------------------
__device__ __forceinline__ float ex2_(float x){ float r; asm("ex2.approx.f32 %0,%1;":"=f"(r):"f"(x)); return r; }
__device__ __forceinline__ float lg2_(float x){ float r; asm("lg2.approx.f32 %0,%1;":"=f"(r):"f"(x)); return r; }
__device__ __forceinline__ float rcp_(float x){ float r; asm("rcp.approx.f32 %0,%1;":"=f"(r):"f"(x)); return r; }

// ---- packed f32x2 helpers (sm_100+) -----------------------------------------
__device__ __forceinline__ ull pack2(float lo, float hi){
  ull r; asm("mov.b64 %0, {%1,%2};" : "=l"(r) : "f"(lo), "f"(hi)); return r;
}
__device__ __forceinline__ void unpack2(ull v, float& lo, float& hi){
  asm("mov.b64 {%0,%1}, %2;" : "=f"(lo), "=f"(hi) : "l"(v));
}
__device__ __forceinline__ ull fma2(ull a, ull b, ull c){
  ull d; asm("fma.rn.f32x2 %0, %1, %2, %3;" : "=l"(d) : "l"(a), "l"(b), "l"(c)); return d;
}
__device__ __forceinline__ ull mul2(ull a, ull b){
  ull d; asm("mul.rn.f32x2 %0, %1, %2;" : "=l"(d) : "l"(a), "l"(b)); return d;
}
__device__ __forceinline__ ull add2(ull a, ull b){
  ull d; asm("add.rn.f32x2 %0, %1, %2;" : "=l"(d) : "l"(a), "l"(b)); return d;
}

__device__ __forceinline__ float dotqk(const ull* qq, const float* kp_f){
  const ulonglong2* kp = (const ulonglong2*)kp_f;
  ulonglong2 kA=kp[0], kB=kp[1], kC=kp[2], kD=kp[3];
  ull d0 = mul2(qq[0],kA.x); d0=fma2(qq[1],kA.y,d0); d0=fma2(qq[2],kB.x,d0); d0=fma2(qq[3],kB.y,d0);
  ull d1 = mul2(qq[4],kC.x); d1=fma2(qq[5],kC.y,d1); d1=fma2(qq[6],kD.x,d1); d1=fma2(qq[7],kD.y,d1);
  float s0,s1,s2,s3; unpack2(d0,s0,s1); unpack2(d1,s2,s3);
  return (s0+s1)+(s2+s3);
}

// dot for two q rows sharing one k row load
__device__ __forceinline__ void dotqk2(const ull* q0, const ull* q1, const float* kp_f,
                                       float& sA, float& sB){
  const ulonglong2* kp = (const ulonglong2*)kp_f;
  ulonglong2 kA=kp[0], kB=kp[1], kC=kp[2], kD=kp[3];
  ull d0 = mul2(q0[0],kA.x); d0=fma2(q0[1],kA.y,d0); d0=fma2(q0[2],kB.x,d0); d0=fma2(q0[3],kB.y,d0);
  ull d1 = mul2(q0[4],kC.x); d1=fma2(q0[5],kC.y,d1); d1=fma2(q0[6],kD.x,d1); d1=fma2(q0[7],kD.y,d1);
  ull e0 = mul2(q1[0],kA.x); e0=fma2(q1[1],kA.y,e0); e0=fma2(q1[2],kB.x,e0); e0=fma2(q1[3],kB.y,e0);
  ull e1 = mul2(q1[4],kC.x); e1=fma2(q1[5],kC.y,e1); e1=fma2(q1[6],kD.x,e1); e1=fma2(q1[7],kD.y,e1);
  float s0,s1,s2,s3; unpack2(d0,s0,s1); unpack2(d1,s2,s3);
  sA = (s0+s1)+(s2+s3);
  float t0,t1,t2,t3; unpack2(e0,t0,t1); unpack2(e1,t2,t3);
  sB = (t0+t1)+(t2+t3);
}

// ---- start conv + skip zero -------------------------------------------------
__global__ __launch_bounds__(256) void start_kernel(const float* __restrict__ x,
                                                    const float* __restrict__ sW,
                                                    const float* __restrict__ sb){
  int i = blockIdx.x*256 + threadIdx.x;
  const int tot = 64*13*CNN;
  if (i < tot){
    int n = i % NN; int r = i / NN;
    int c = r & 31; r >>= 5;
    int t = r % 13; int b = r / 13;
    float v0 = x[((b*2+0)*NN + n)*13 + t];
    float v1 = x[((b*2+1)*NN + n)*13 + t];
    g_X0[i] = fmaf(sW[c*2], v0, fmaf(sW[c*2+1], v1, sb[c]));
  } else {
    int j = i - tot;
    if (j < 64*256*NN) g_skip[j] = 0.f;
  }
}

// ---- fused layer kernel -----------------------------------------------------
#define OFF_K     7040
#define OFF_MXP   14080    // [4][352]
#define OFF_ZP    15488    // [4][352]
#define OFF_GX    16896    // [352][36]
#define OFF_W     29568    // staged weights (max 4192)
#define OFF_ROW   33760    // [352]
#define LAYER_SMEM_BYTES (34112*4)

__global__ __launch_bounds__(NT,1) void layer_kernel(
    int layer, int dil, int do_att, int parity,
    const float* __restrict__ fW,  const float* __restrict__ fb,
    const float* __restrict__ gW,  const float* __restrict__ gb,
    const float* __restrict__ skW, const float* __restrict__ skb,
    const float* __restrict__ qW,  const float* __restrict__ qb,
    const float* __restrict__ kW,  const float* __restrict__ kb,
    const float* __restrict__ mW,  const float* __restrict__ mb,
    const float* __restrict__ bng, const float* __restrict__ bnb,
    const float* __restrict__ bnm, const float* __restrict__ bnv,
    const float* __restrict__ emb)
{
  extern __shared__ __align__(16) float sm[];
  const float* __restrict__ Xin  = parity ? g_X1 : g_X0;
  float* __restrict__       Xout = parity ? g_X0 : g_X1;
  const int t = blockIdx.x, b = blockIdx.y, tid = threadIdx.x;
  const int Tout = gridDim.x;
  const int n = tid % 352;
  const int h = tid / 352;
  const int last_t = (t == Tout-1);
  const size_t tile = (size_t)(b*13 + t);

  float* s_swt = sm;               // [32][256] (phase 0..1b)
  float* s_q   = sm;               // [352][20] (phases 2-3)
  float* s_k   = sm + OFF_K;       // [352][20]
  float* s_mxp = sm + OFF_MXP;     // [4][352]
  float* s_zp  = sm + OFF_ZP;      // [4][352]
  float* s_xa  = sm;               // [352][36] (after xa loop)
  float* s_gx  = sm + OFF_GX;      // [352][36]
  float* wreg  = sm + OFF_W;
  float* s_row = sm + OFF_ROW;

  // ---- phase 0: stage gated weights [ci][kind f0,f1,g0,g1][co] + biases -----
  for (int idx = tid; idx < 4096; idx += NT){
    int ci = idx>>7, r = idx&127, kind = r>>5, co = r&31;
    const float* src = (kind < 2) ? fW : gW;
    wreg[idx] = src[((layer*32+co)*32+ci)*2 + (kind & 1)];
  }
  if (tid < 64) wreg[4096+tid] = (tid<32) ? fb[layer*32+tid] : gb[layer*32+tid-32];
  if (last_t){
    for (int idx = tid; idx < 8192; idx += NT){
      int ci = idx>>8, o = idx&255;
      s_swt[idx] = skW[(layer*256+o)*32 + ci];
    }
  }
  __syncthreads();

  // ---- phase 1: gated conv (packed f32x2), half the channels per thread -----
  const int base_in = (b*13 + t)*CNN;
  if (n < NN){
    const float* xin = Xin + base_in + n;
    const float* xrn = xin + dil*CNN;
    ull f2[8], g2[8];
    {
      const ulonglong2* fbp = (const ulonglong2*)(wreg + 4096 + 16*h);
      const ulonglong2* gbp = (const ulonglong2*)(wreg + 4128 + 16*h);
      #pragma unroll
      for (int p=0;p<4;p++){ ulonglong2 a=fbp[p], c=gbp[p]; f2[2*p]=a.x; f2[2*p+1]=a.y; g2[2*p]=c.x; g2[2*p+1]=c.y; }
    }
    #pragma unroll 4
    for (int ci=0; ci<32; ci++){
      float xl = xin[ci*NN], xr = xrn[ci*NN];
      ull xl2 = pack2(xl,xl), xr2 = pack2(xr,xr);
      const ulonglong2* p0 = (const ulonglong2*)(wreg + ci*128      + 16*h);
      const ulonglong2* p1 = (const ulonglong2*)(wreg + ci*128 + 32 + 16*h);
      const ulonglong2* p2 = (const ulonglong2*)(wreg + ci*128 + 64 + 16*h);
      const ulonglong2* p3 = (const ulonglong2*)(wreg + ci*128 + 96 + 16*h);
      #pragma unroll
      for (int p4=0;p4<4;p4++){
        ulonglong2 a=p0[p4], bb=p1[p4], c=p2[p4], d=p3[p4];
        f2[2*p4]   = fma2(xl2, a.x,  f2[2*p4]);   f2[2*p4+1] = fma2(xl2, a.y,  f2[2*p4+1]);
        f2[2*p4]   = fma2(xr2, bb.x, f2[2*p4]);   f2[2*p4+1] = fma2(xr2, bb.y, f2[2*p4+1]);
        g2[2*p4]   = fma2(xl2, c.x,  g2[2*p4]);   g2[2*p4+1] = fma2(xl2, c.y,  g2[2*p4+1]);
        g2[2*p4]   = fma2(xr2, d.x,  g2[2*p4]);   g2[2*p4+1] = fma2(xr2, d.y,  g2[2*p4+1]);
      }
    }
    #pragma unroll
    for (int p=0;p<8;p++){
      float fa,fb2, ga,gb2;
      unpack2(f2[p], fa, fb2); unpack2(g2[p], ga, gb2);
      float efa = ex2_(-2.88539008f*fa), ega = ex2_(-1.44269504f*ga);
      float efb = ex2_(-2.88539008f*fb2), egb = ex2_(-1.44269504f*gb2);
      s_gx[n*36 + 16*h + 2*p]   = (1.f - efa) * rcp_((1.f + efa)*(1.f + ega));
      s_gx[n*36 + 16*h + 2*p+1] = (1.f - efb) * rcp_((1.f + efb)*(1.f + egb));
    }
  }
  __syncthreads();

  // ---- stage attention-phase weights ----------------------------------------
  if (do_att){
    for (int idx = tid; idx < 1536; idx += NT){
      int half = (idx >= 768) ? 1 : 0;
      int r = idx - half*768; int cin = r>>4, d = r&15;
      wreg[idx] = (half ? kW : qW)[(layer*16+d)*48 + cin];
    }
    if (tid < 32) wreg[1536+tid] = (tid<16) ? qb[layer*16+tid] : kb[layer*16+tid-16];
    for (int idx = tid; idx < 2048; idx += NT){
      int c = idx>>5, o = idx&31;
      wreg[1568+idx] = mW[(layer*32+o)*64 + c];
    }
    if (tid < 32){
      wreg[3616+tid] = mb[layer*32+tid];
      float sc = bng[layer*32+tid] * rsqrtf(bnv[layer*32+tid] + 1e-5f);
      wreg[3648+tid] = sc;
      wreg[3680+tid] = bnb[layer*32+tid] - bnm[layer*32+tid]*sc;
    }
  }

  // ---- phase 1b: skip contribution (only last time index) -------------------
  if (last_t && n < NN){
    float* skp = g_skip + b*256*NN + n;
    const float4* gxv = (const float4*)(s_gx + n*36);
    #pragma unroll 1
    for (int og=0; og<4; og++){
      int ot = 4*h + og;
      float acc[32];
      #pragma unroll
      for (int j=0;j<32;j++) acc[j] = skb[layer*256 + ot*32 + j];
      #pragma unroll 2
      for (int ci4=0; ci4<8; ci4++){
        float4 g4 = gxv[ci4];
        #pragma unroll
        for (int jj=0; jj<4; jj++){
          float xv = (jj==0)?g4.x:(jj==1)?g4.y:(jj==2)?g4.z:g4.w;
          const float4* wv = (const float4*)(s_swt + (ci4*4+jj)*256 + ot*32);
          #pragma unroll
          for (int j4=0;j4<8;j4++){
            float4 w = wv[j4];
            acc[4*j4+0]=fmaf(w.x,xv,acc[4*j4+0]); acc[4*j4+1]=fmaf(w.y,xv,acc[4*j4+1]);
            acc[4*j4+2]=fmaf(w.z,xv,acc[4*j4+2]); acc[4*j4+3]=fmaf(w.w,xv,acc[4*j4+3]);
          }
        }
      }
      #pragma unroll
      for (int j=0;j<32;j++) skp[(ot*32+j)*NN] += acc[j];
    }
  }
  if (!do_att) return;
  __syncthreads();

  // ---- phase 2: h=0 -> q (log2e/4 folded), h=1 -> k (packed) ----------------
  if (n < NN){
    ull a2[8];
    const float* wb = wreg + 768*h;
    {
      const ulonglong2* bp2 = (const ulonglong2*)(wreg + 1536 + 16*h);
      #pragma unroll
      for (int p=0;p<4;p++){ ulonglong2 v=bp2[p]; a2[2*p]=v.x; a2[2*p+1]=v.y; }
    }
    const float4* gxv = (const float4*)(s_gx + n*36);
    #pragma unroll 2
    for (int ci4=0; ci4<8; ci4++){
      float4 g4 = gxv[ci4];
      #pragma unroll
      for (int jj=0; jj<4; jj++){
        float xv = (jj==0)?g4.x:(jj==1)?g4.y:(jj==2)?g4.z:g4.w;
        ull xv2 = pack2(xv,xv);
        const ulonglong2* wv = (const ulonglong2*)(wb + (ci4*4+jj)*16);
        ulonglong2 wA=wv[0], wB=wv[1], wC=wv[2], wD=wv[3];
        a2[0]=fma2(xv2,wA.x,a2[0]); a2[1]=fma2(xv2,wA.y,a2[1]);
        a2[2]=fma2(xv2,wB.x,a2[2]); a2[3]=fma2(xv2,wB.y,a2[3]);
        a2[4]=fma2(xv2,wC.x,a2[4]); a2[5]=fma2(xv2,wC.y,a2[5]);
        a2[6]=fma2(xv2,wD.x,a2[6]); a2[7]=fma2(xv2,wD.y,a2[7]);
      }
    }
    #pragma unroll 4
    for (int e=0; e<16; e++){
      float xv = emb[e*NN+n];
      ull xv2 = pack2(xv,xv);
      const ulonglong2* wv = (const ulonglong2*)(wb + (32+e)*16);
      ulonglong2 wA=wv[0], wB=wv[1], wC=wv[2], wD=wv[3];
      a2[0]=fma2(xv2,wA.x,a2[0]); a2[1]=fma2(xv2,wA.y,a2[1]);
      a2[2]=fma2(xv2,wB.x,a2[2]); a2[3]=fma2(xv2,wB.y,a2[3]);
      a2[4]=fma2(xv2,wC.x,a2[4]); a2[5]=fma2(xv2,wC.y,a2[5]);
      a2[6]=fma2(xv2,wD.x,a2[6]); a2[7]=fma2(xv2,wD.y,a2[7]);
    }
    if (h == 0){
      ull qsc2 = pack2(0.36067376f, 0.36067376f);
      ull* qp = (ull*)(s_q + n*20);
      #pragma unroll
      for (int p=0;p<8;p++) qp[p] = mul2(a2[p], qsc2);
    } else {
      ull* kp = (ull*)(s_k + n*20);
      #pragma unroll
      for (int p=0;p<8;p++) kp[p] = a2[p];
    }
  }
  __syncthreads();

  // ---- phase 3: scores ONCE; 2-row x quarter-column blocking ----------------
  // thread = (column-quarter pq, row-pair pr). k-row loads shared by 2 rows.
  {
    const int pq = tid / 176;          // 0..3
    const int pr = tid - pq*176;       // 0..175
    const int r0 = 2*pr, r1 = r0 + 1;
    if (r0 < NN){
      ull q0[8], q1[8];
      {
        const ulonglong2* qp0 = (const ulonglong2*)(s_q + r0*20);
        const ulonglong2* qp1 = (const ulonglong2*)(s_q + r1*20);
        #pragma unroll
        for (int p=0;p<4;p++){ ulonglong2 v=qp0[p]; q0[2*p]=v.x; q0[2*p+1]=v.y; }
        #pragma unroll
        for (int p=0;p<4;p++){ ulonglong2 v=qp1[p]; q1[2*p]=v.x; q1[2*p+1]=v.y; }
      }
      float* trow0 = g_sc + tile*SCT + (size_t)r0*328;
      float* trow1 = trow0 + 328;
      const int c0 = pq*84;
      const int nvec = (pq < 3) ? 21 : 18;
      float mx0=-1e30f, Z0=0.f, mx1=-1e30f, Z1=0.f;
      #pragma unroll 1
      for (int v=0; v<nvec; v++){
        int c = c0 + 4*v;
        float a0,a1,a2,a3, b0,b1,b2,b3;
        dotqk2(q0,q1, s_k + (c+0)*20, a0,b0);
        dotqk2(q0,q1, s_k + (c+1)*20, a1,b1);
        dotqk2(q0,q1, s_k + (c+2)*20, a2,b2);
        dotqk2(q0,q1, s_k + (c+3)*20, a3,b3);
        *(float4*)(trow0 + c) = make_float4(a0,a1,a2,a3);
        if (r1 < NN) *(float4*)(trow1 + c) = make_float4(b0,b1,b2,b3);
        float nm;
        nm=fmaxf(mx0,a0); Z0=fmaf(Z0,ex2_(mx0-nm),ex2_(a0-nm)); mx0=nm;
        nm=fmaxf(mx1,b0); Z1=fmaf(Z1,ex2_(mx1-nm),ex2_(b0-nm)); mx1=nm;
        nm=fmaxf(mx0,a1); Z0=fmaf(Z0,ex2_(mx0-nm),ex2_(a1-nm)); mx0=nm;
        nm=fmaxf(mx1,b1); Z1=fmaf(Z1,ex2_(mx1-nm),ex2_(b1-nm)); mx1=nm;
        nm=fmaxf(mx0,a2); Z0=fmaf(Z0,ex2_(mx0-nm),ex2_(a2-nm)); mx0=nm;
        nm=fmaxf(mx1,b2); Z1=fmaf(Z1,ex2_(mx1-nm),ex2_(b2-nm)); mx1=nm;
        nm=fmaxf(mx0,a3); Z0=fmaf(Z0,ex2_(mx0-nm),ex2_(a3-nm)); mx0=nm;
        nm=fmaxf(mx1,b3); Z1=fmaf(Z1,ex2_(mx1-nm),ex2_(b3-nm)); mx1=nm;
      }
      if (pq == 3){
        float sA, sB;
        dotqk2(q0,q1, s_k + 324*20, sA,sB);
        trow0[324] = sA;
        if (r1 < NN) trow1[324] = sB;
        float nm;
        nm=fmaxf(mx0,sA); Z0=fmaf(Z0,ex2_(mx0-nm),ex2_(sA-nm)); mx0=nm;
        nm=fmaxf(mx1,sB); Z1=fmaf(Z1,ex2_(mx1-nm),ex2_(sB-nm)); mx1=nm;
      }
      s_mxp[pq*352 + r0] = mx0; s_zp[pq*352 + r0] = Z0;
      if (r1 < NN){ s_mxp[pq*352 + r1] = mx1; s_zp[pq*352 + r1] = Z1; }
    }
  }
  __syncthreads();
  if (tid < NN){
    float mx = s_mxp[tid], Z = s_zp[tid];
    #pragma unroll
    for (int qd=1; qd<4; qd++){
      float m2 = s_mxp[qd*352+tid], z2 = s_zp[qd*352+tid];
      float nm = fmaxf(mx, m2);
      Z = fmaf(Z, ex2_(mx-nm), z2*ex2_(m2-nm));
      mx = nm;
    }
    s_row[tid] = mx + lg2_(Z);
  }
  __syncthreads();

  // ---- phase 4: weighted sum from stored scores (clean loop, no guards) -----
  const int warp = tid >> 5, lane = tid & 31;
  const int bmh = warp & 1;
  const int bp  = (warp >> 1)*16 + (lane >> 1);   // 0..175
  const int bch = lane & 1;
  const int j1  = 2*bp, j2 = 2*bp + 1;

  ull xaA[8], xaB[8];
  #pragma unroll
  for (int p=0;p<8;p++){ xaA[p]=0ULL; xaB[p]=0ULL; }
  {
    const int mbase  = bmh ? 163 : 0;
    const int mcount = bmh ? 162 : 163;   // m=325 would be invalid -> dropped
    const float* sp2 = g_sc + tile*SCT + (size_t)mbase*328 + j1;
    #pragma unroll 8
    for (int i=0; i<mcount; i++){
      int m = mbase + i;
      float2 sc = *(const float2*)(sp2 + (size_t)i*328);
      float rw = s_row[m];
      float w1 = ex2_(sc.x - rw), w2 = ex2_(sc.y - rw);
      ull w12 = pack2(w1,w1), w22 = pack2(w2,w2);
      const ulonglong2* gv = (const ulonglong2*)(s_gx + m*36 + 16*bch);
      ulonglong2 gA=gv[0], gB=gv[1], gC=gv[2], gD=gv[3];
      xaA[0]=fma2(w12,gA.x,xaA[0]); xaA[1]=fma2(w12,gA.y,xaA[1]);
      xaA[2]=fma2(w12,gB.x,xaA[2]); xaA[3]=fma2(w12,gB.y,xaA[3]);
      xaA[4]=fma2(w12,gC.x,xaA[4]); xaA[5]=fma2(w12,gC.y,xaA[5]);
      xaA[6]=fma2(w12,gD.x,xaA[6]); xaA[7]=fma2(w12,gD.y,xaA[7]);
      xaB[0]=fma2(w22,gA.x,xaB[0]); xaB[1]=fma2(w22,gA.y,xaB[1]);
      xaB[2]=fma2(w22,gB.x,xaB[2]); xaB[3]=fma2(w22,gB.y,xaB[3]);
      xaB[4]=fma2(w22,gC.x,xaB[4]); xaB[5]=fma2(w22,gC.y,xaB[5]);
      xaB[6]=fma2(w22,gD.x,xaB[6]); xaB[7]=fma2(w22,gD.y,xaB[7]);
    }
  }
  __syncthreads();                  // attention reads of s_q/s_k region done
  if (bmh == 0 && j1 < NN){
    ulonglong2* xp1 = (ulonglong2*)(s_xa + j1*36 + 16*bch);
    xp1[0]=make_ulonglong2(xaA[0],xaA[1]); xp1[1]=make_ulonglong2(xaA[2],xaA[3]);
    xp1[2]=make_ulonglong2(xaA[4],xaA[5]); xp1[3]=make_ulonglong2(xaA[6],xaA[7]);
    if (j2 < NN){
      ulonglong2* xp2 = (ulonglong2*)(s_xa + j2*36 + 16*bch);
      xp2[0]=make_ulonglong2(xaB[0],xaB[1]); xp2[1]=make_ulonglong2(xaB[2],xaB[3]);
      xp2[2]=make_ulonglong2(xaB[4],xaB[5]); xp2[3]=make_ulonglong2(xaB[6],xaB[7]);
    }
  }
  __syncthreads();
  if (bmh == 1 && j1 < NN){
    ull* xp1 = (ull*)(s_xa + j1*36 + 16*bch);
    #pragma unroll
    for (int p=0;p<8;p++) xp1[p] = add2(xp1[p], xaA[p]);
    if (j2 < NN){
      ull* xp2 = (ull*)(s_xa + j2*36 + 16*bch);
      #pragma unroll
      for (int p=0;p<8;p++) xp2[p] = add2(xp2[p], xaB[p]);
    }
  }
  __syncthreads();

  // ---- phase 5: mlp (packed) + residual + BN ---------------------------------
  if (n < NN){
    ull o2[8];
    {
      const ulonglong2* bp2 = (const ulonglong2*)(wreg + 3616 + 16*h);
      #pragma unroll
      for (int p=0;p<4;p++){ ulonglong2 v=bp2[p]; o2[2*p]=v.x; o2[2*p+1]=v.y; }
    }
    const float4* gxv = (const float4*)(s_gx + n*36);
    const float4* xav = (const float4*)(s_xa + n*36);
    #pragma unroll 2
    for (int ci4=0; ci4<8; ci4++){
      float4 g4 = gxv[ci4];
      #pragma unroll
      for (int jj=0; jj<4; jj++){
        float xv = (jj==0)?g4.x:(jj==1)?g4.y:(jj==2)?g4.z:g4.w;
        ull xv2 = pack2(xv,xv);
        const ulonglong2* wv = (const ulonglong2*)(wreg + 1568 + (ci4*4+jj)*32 + 16*h);
        ulonglong2 wA=wv[0], wB=wv[1];
        o2[0]=fma2(xv2,wA.x,o2[0]); o2[1]=fma2(xv2,wA.y,o2[1]);
        o2[2]=fma2(xv2,wB.x,o2[2]); o2[3]=fma2(xv2,wB.y,o2[3]);
        wA=wv[2]; wB=wv[3];
        o2[4]=fma2(xv2,wA.x,o2[4]); o2[5]=fma2(xv2,wA.y,o2[5]);
        o2[6]=fma2(xv2,wB.x,o2[6]); o2[7]=fma2(xv2,wB.y,o2[7]);
      }
    }
    #pragma unroll 2
    for (int ci4=0; ci4<8; ci4++){
      float4 g4 = xav[ci4];
      #pragma unroll
      for (int jj=0; jj<4; jj++){
        float xv = (jj==0)?g4.x:(jj==1)?g4.y:(jj==2)?g4.z:g4.w;
        ull xv2 = pack2(xv,xv);
        const ulonglong2* wv = (const ulonglong2*)(wreg + 1568 + (32+ci4*4+jj)*32 + 16*h);
        ulonglong2 wA=wv[0], wB=wv[1];
        o2[0]=fma2(xv2,wA.x,o2[0]); o2[1]=fma2(xv2,wA.y,o2[1]);
        o2[2]=fma2(xv2,wB.x,o2[2]); o2[3]=fma2(xv2,wB.y,o2[3]);
        wA=wv[2]; wB=wv[3];
        o2[4]=fma2(xv2,wA.x,o2[4]); o2[5]=fma2(xv2,wA.y,o2[5]);
        o2[6]=fma2(xv2,wB.x,o2[6]); o2[7]=fma2(xv2,wB.y,o2[7]);
      }
    }
    const float* rin = Xin + base_in + dil*CNN + n;
    float* outp = Xout + base_in + n;
    #pragma unroll
    for (int p=0; p<8; p++){
      float va, vb; unpack2(o2[p], va, vb);
      int c0 = 16*h + 2*p, c1 = c0 + 1;
      float v0 = va + rin[c0*NN];
      float v1 = vb + rin[c1*NN];
      outp[c0*NN] = fmaf(v0, wreg[3648+c0], wreg[3680+c0]);
      outp[c1*NN] = fmaf(v1, wreg[3648+c1], wreg[3680+c1]);
    }
  }
}

// ---- head: relu(skip) -> relu(512) -> 12 ------------------------------------
#define H_SS 0
#define H_W1 16384
#define H_H  32832
#define H_W2 37184
#define H_B1 43328
#define HEAD_SMEM_BYTES (43840*4)

__global__ __launch_bounds__(256,1) void head_kernel(
    const float* __restrict__ w1, const float* __restrict__ b1,
    const float* __restrict__ w2, const float* __restrict__ b2,
    float* __restrict__ out)
{
  extern __shared__ __align__(16) float sm[];
  float* s_s = sm + H_SS;   // [256][64]
  float* w1s = sm + H_W1;   // [64][257]
  float* h_s = sm + H_H;    // [64][68]
  float* w2t = sm + H_W2;   // [512][12]
  float* b1s = sm + H_B1;   // [512]
  const int tid = threadIdx.x;
  const int p0 = blockIdx.x*64;

  for (int idx = tid; idx < 16384; idx += 256){
    int c = idx>>6, j = idx&63, p = p0 + j;
    int b = p/NN, nn = p - b*NN;
    s_s[idx] = fmaxf(g_skip[(b*256+c)*NN + nn], 0.f);
  }
  for (int idx = tid; idx < 6144; idx += 256){
    int o = idx/12, oo = idx - o*12;
    w2t[idx] = w2[oo*512 + o];
  }
  for (int idx = tid; idx < 512; idx += 256) b1s[idx] = b1[idx];

  const int op  = tid & 63, jg = tid >> 6;
  const int oo  = tid % 12, j0 = (tid/12)*4;
  float accO[4] = {0.f,0.f,0.f,0.f};

  for (int ot = 0; ot < 8; ot++){
    __syncthreads();
    for (int idx = tid; idx < 16384; idx += 256){
      int o = idx>>8, c = idx&255;
      w1s[o*257+c] = w1[(ot*64+o)*256 + c];
    }
    __syncthreads();
    {
      float acc[16];
      float bv = b1s[ot*64+op];
      #pragma unroll
      for (int k=0;k<16;k++) acc[k]=bv;
      #pragma unroll 2
      for (int c=0; c<256; c++){
        float w = w1s[op*257+c];
        const float4* sp = (const float4*)(s_s + c*64 + jg*16);
        #pragma unroll
        for (int k4=0;k4<4;k4++){
          float4 s4 = sp[k4];
          acc[4*k4+0]=fmaf(w,s4.x,acc[4*k4+0]); acc[4*k4+1]=fmaf(w,s4.y,acc[4*k4+1]);
          acc[4*k4+2]=fmaf(w,s4.z,acc[4*k4+2]); acc[4*k4+3]=fmaf(w,s4.w,acc[4*k4+3]);
        }
      }
      float4* hp = (float4*)(h_s + op*68 + jg*16);
      #pragma unroll
      for (int k4=0;k4<4;k4++)
        hp[k4] = make_float4(fmaxf(acc[4*k4+0],0.f), fmaxf(acc[4*k4+1],0.f),
                             fmaxf(acc[4*k4+2],0.f), fmaxf(acc[4*k4+3],0.f));
    }
    __syncthreads();
    if (tid < 192){
      #pragma unroll 4
      for (int o=0; o<64; o++){
        float w = w2t[(ot*64+o)*12 + oo];
        const float4* hp = (const float4*)(h_s + o*68 + j0);
        float4 h4 = hp[0];
        accO[0]=fmaf(w,h4.x,accO[0]); accO[1]=fmaf(w,h4.y,accO[1]);
        accO[2]=fmaf(w,h4.z,accO[2]); accO[3]=fmaf(w,h4.w,accO[3]);
      }
    }
  }
  if (tid < 192){
    float bb = b2[oo];
    #pragma unroll
    for (int k=0;k<4;k++){
      int p = p0 + j0 + k;
      int b = p/NN, nn = p - b*NN;
      out[(b*12+oo)*NN + nn] = accO[k] + bb;
    }
  }
}

// ---- host -------------------------------------------------------------------
extern "C" void kernel_launch(void* const* d_in, const int* in_sizes, int n_in,
                              void* d_out, int out_size){
  const float* x    = (const float*)d_in[0];
  const float* emb  = (const float*)d_in[1];
  const float* stW  = (const float*)d_in[2];
  const float* stb  = (const float*)d_in[3];
  const float* fW   = (const float*)d_in[4];
  const float* fb   = (const float*)d_in[5];
  const float* gW   = (const float*)d_in[6];
  const float* gb   = (const float*)d_in[7];
  const float* skW  = (const float*)d_in[8];
  const float* skb  = (const float*)d_in[9];
  const float* qW   = (const float*)d_in[10];
  const float* qb   = (const float*)d_in[11];
  const float* kW   = (const float*)d_in[12];
  const float* kb   = (const float*)d_in[13];
  const float* mW   = (const float*)d_in[14];
  const float* mb   = (const float*)d_in[15];
  const float* bng  = (const float*)d_in[16];
  const float* bnb  = (const float*)d_in[17];
  const float* bnm  = (const float*)d_in[18];
  const float* bnv  = (const float*)d_in[19];
  const float* e1W  = (const float*)d_in[20];
  const float* e1b  = (const float*)d_in[21];
  const float* e2W  = (const float*)d_in[22];
  const float* e2b  = (const float*)d_in[23];
  float* out = (float*)d_out;

  cudaFuncSetAttribute(layer_kernel, cudaFuncAttributeMaxDynamicSharedMemorySize, LAYER_SMEM_BYTES);
  cudaFuncSetAttribute(head_kernel,  cudaFuncAttributeMaxDynamicSharedMemorySize, HEAD_SMEM_BYTES);

  start_kernel<<<54600, 256>>>(x, stW, stb);

  const int dil[8]  = {1,2,1,2,1,2,1,2};
  const int Tout[8] = {12,10,9,7,6,4,3,1};
  for (int i = 0; i < 8; i++){
    layer_kernel<<<dim3(Tout[i], 64), NT, LAYER_SMEM_BYTES>>>(
        i, dil[i], (i != 7) ? 1 : 0, i & 1,
        fW, fb, gW, gb, skW, skb, qW, qb, kW, kb, mW, mb,
        bng, bnb, bnm, bnv, emb);
  }

  head_kernel<<<325, 256, HEAD_SMEM_BYTES>>>(e1W, e1b, e2W, e2b, out);
}

// round 13
// speedup vs baseline: 1.0620x; 1.0620x over previous
#include <cuda_runtime.h>

#define NN 325
#define CNN (32*NN)
#define NT 704          // 2 threads per node slot for phases 1/2/5

typedef unsigned long long ull;

static __device__ float g_X0[64*13*CNN];
static __device__ float g_X1[64*13*CNN];
static __device__ float g_skip[64*256*NN];
#define SCT (328*328)
static __device__ float g_sc[832u*SCT];   // per-(b,t) score scratch, L2-resident working set

// ---- MUFU helpers (SFU pipe; rel err ~1e-6) ---------------------------------
__device__ __forceinline__ float ex2_(float x){ float r; asm("ex2.approx.f32 %0,%1;":"=f"(r):"f"(x)); return r; }
__device__ __forceinline__ float lg2_(float x){ float r; asm("lg2.approx.f32 %0,%1;":"=f"(r):"f"(x)); return r; }
__device__ __forceinline__ float rcp_(float x){ float r; asm("rcp.approx.f32 %0,%1;":"=f"(r):"f"(x)); return r; }

// ---- packed f32x2 helpers (sm_100+) -----------------------------------------
__device__ __forceinline__ ull pack2(float lo, float hi){
  ull r; asm("mov.b64 %0, {%1,%2};" : "=l"(r) : "f"(lo), "f"(hi)); return r;
}
__device__ __forceinline__ void unpack2(ull v, float& lo, float& hi){
  asm("mov.b64 {%0,%1}, %2;" : "=f"(lo), "=f"(hi) : "l"(v));
}
__device__ __forceinline__ ull fma2(ull a, ull b, ull c){
  ull d; asm("fma.rn.f32x2 %0, %1, %2, %3;" : "=l"(d) : "l"(a), "l"(b), "l"(c)); return d;
}
__device__ __forceinline__ ull mul2(ull a, ull b){
  ull d; asm("mul.rn.f32x2 %0, %1, %2;" : "=l"(d) : "l"(a), "l"(b)); return d;
}
__device__ __forceinline__ ull add2(ull a, ull b){
  ull d; asm("add.rn.f32x2 %0, %1, %2;" : "=l"(d) : "l"(a), "l"(b)); return d;
}

__device__ __forceinline__ float dotqk(const ull* qq, const float* kp_f){
  const ulonglong2* kp = (const ulonglong2*)kp_f;
  ulonglong2 kA=kp[0], kB=kp[1], kC=kp[2], kD=kp[3];
  ull d0 = mul2(qq[0],kA.x); d0=fma2(qq[1],kA.y,d0); d0=fma2(qq[2],kB.x,d0); d0=fma2(qq[3],kB.y,d0);
  ull d1 = mul2(qq[4],kC.x); d1=fma2(qq[5],kC.y,d1); d1=fma2(qq[6],kD.x,d1); d1=fma2(qq[7],kD.y,d1);
  float s0,s1,s2,s3; unpack2(d0,s0,s1); unpack2(d1,s2,s3);
  return (s0+s1)+(s2+s3);
}

// ---- start conv + skip zero -------------------------------------------------
__global__ __launch_bounds__(256) void start_kernel(const float* __restrict__ x,
                                                    const float* __restrict__ sW,
                                                    const float* __restrict__ sb){
  int i = blockIdx.x*256 + threadIdx.x;
  const int tot = 64*13*CNN;
  if (i < tot){
    int n = i % NN; int r = i / NN;
    int c = r & 31; r >>= 5;
    int t = r % 13; int b = r / 13;
    float v0 = x[((b*2+0)*NN + n)*13 + t];
    float v1 = x[((b*2+1)*NN + n)*13 + t];
    g_X0[i] = fmaf(sW[c*2], v0, fmaf(sW[c*2+1], v1, sb[c]));
  } else {
    int j = i - tot;
    if (j < 64*256*NN) g_skip[j] = 0.f;
  }
}

// ---- fused layer kernel -----------------------------------------------------
#define OFF_K     7040
#define OFF_MXP   14080
#define OFF_ZP    14784
#define OFF_GX    15488    // [352][36]
#define OFF_W     28160    // staged weights (max 4192)
#define OFF_ROW   32352    // [352]
#define LAYER_SMEM_BYTES (32704*4)

__global__ __launch_bounds__(NT,1) void layer_kernel(
    int layer, int dil, int do_att, int parity,
    const float* __restrict__ fW,  const float* __restrict__ fb,
    const float* __restrict__ gW,  const float* __restrict__ gb,
    const float* __restrict__ skW, const float* __restrict__ skb,
    const float* __restrict__ qW,  const float* __restrict__ qb,
    const float* __restrict__ kW,  const float* __restrict__ kb,
    const float* __restrict__ mW,  const float* __restrict__ mb,
    const float* __restrict__ bng, const float* __restrict__ bnb,
    const float* __restrict__ bnm, const float* __restrict__ bnv,
    const float* __restrict__ emb)
{
  extern __shared__ __align__(16) float sm[];
  const float* __restrict__ Xin  = parity ? g_X1 : g_X0;
  float* __restrict__       Xout = parity ? g_X0 : g_X1;
  const int t = blockIdx.x, b = blockIdx.y, tid = threadIdx.x;
  const int Tout = gridDim.x;
  const int n = tid % 352;
  const int h = tid / 352;
  const int last_t = (t == Tout-1);
  const size_t tile = (size_t)(b*13 + t);

  float* s_swt = sm;               // [32][256] (phase 0..1b)
  float* s_q   = sm;               // [352][20] (phases 2-3)
  float* s_k   = sm + OFF_K;       // [352][20]
  float* s_mxp = sm + OFF_MXP;     // [2][352]
  float* s_zp  = sm + OFF_ZP;      // [2][352]
  float* s_xa  = sm;               // [352][36] (after xa loop)
  float* s_gx  = sm + OFF_GX;      // [352][36]
  float* wreg  = sm + OFF_W;
  float* s_row = sm + OFF_ROW;

  // ---- phase 0: stage gated weights [ci][kind f0,f1,g0,g1][co] + biases -----
  for (int idx = tid; idx < 4096; idx += NT){
    int ci = idx>>7, r = idx&127, kind = r>>5, co = r&31;
    const float* src = (kind < 2) ? fW : gW;
    wreg[idx] = src[((layer*32+co)*32+ci)*2 + (kind & 1)];
  }
  if (tid < 64) wreg[4096+tid] = (tid<32) ? fb[layer*32+tid] : gb[layer*32+tid-32];
  if (last_t){
    for (int idx = tid; idx < 8192; idx += NT){
      int ci = idx>>8, o = idx&255;
      s_swt[idx] = skW[(layer*256+o)*32 + ci];
    }
  }
  __syncthreads();

  // ---- phase 1: gated conv (packed f32x2), half the channels per thread -----
  const int base_in = (b*13 + t)*CNN;
  if (n < NN){
    const float* xin = Xin + base_in + n;
    const float* xrn = xin + dil*CNN;
    ull f2[8], g2[8];
    {
      const ulonglong2* fbp = (const ulonglong2*)(wreg + 4096 + 16*h);
      const ulonglong2* gbp = (const ulonglong2*)(wreg + 4128 + 16*h);
      #pragma unroll
      for (int p=0;p<4;p++){ ulonglong2 a=fbp[p], c=gbp[p]; f2[2*p]=a.x; f2[2*p+1]=a.y; g2[2*p]=c.x; g2[2*p+1]=c.y; }
    }
    #pragma unroll 4
    for (int ci=0; ci<32; ci++){
      float xl = xin[ci*NN], xr = xrn[ci*NN];
      ull xl2 = pack2(xl,xl), xr2 = pack2(xr,xr);
      const ulonglong2* p0 = (const ulonglong2*)(wreg + ci*128      + 16*h);
      const ulonglong2* p1 = (const ulonglong2*)(wreg + ci*128 + 32 + 16*h);
      const ulonglong2* p2 = (const ulonglong2*)(wreg + ci*128 + 64 + 16*h);
      const ulonglong2* p3 = (const ulonglong2*)(wreg + ci*128 + 96 + 16*h);
      #pragma unroll
      for (int p4=0;p4<4;p4++){
        ulonglong2 a=p0[p4], bb=p1[p4], c=p2[p4], d=p3[p4];
        f2[2*p4]   = fma2(xl2, a.x,  f2[2*p4]);   f2[2*p4+1] = fma2(xl2, a.y,  f2[2*p4+1]);
        f2[2*p4]   = fma2(xr2, bb.x, f2[2*p4]);   f2[2*p4+1] = fma2(xr2, bb.y, f2[2*p4+1]);
        g2[2*p4]   = fma2(xl2, c.x,  g2[2*p4]);   g2[2*p4+1] = fma2(xl2, c.y,  g2[2*p4+1]);
        g2[2*p4]   = fma2(xr2, d.x,  g2[2*p4]);   g2[2*p4+1] = fma2(xr2, d.y,  g2[2*p4+1]);
      }
    }
    #pragma unroll
    for (int p=0;p<8;p++){
      float fa,fb2, ga,gb2;
      unpack2(f2[p], fa, fb2); unpack2(g2[p], ga, gb2);
      float efa = ex2_(-2.88539008f*fa), ega = ex2_(-1.44269504f*ga);
      float efb = ex2_(-2.88539008f*fb2), egb = ex2_(-1.44269504f*gb2);
      s_gx[n*36 + 16*h + 2*p]   = (1.f - efa) * rcp_((1.f + efa)*(1.f + ega));
      s_gx[n*36 + 16*h + 2*p+1] = (1.f - efb) * rcp_((1.f + efb)*(1.f + egb));
    }
  }
  __syncthreads();

  // ---- stage attention-phase weights ----------------------------------------
  if (do_att){
    for (int idx = tid; idx < 1536; idx += NT){
      int half = (idx >= 768) ? 1 : 0;
      int r = idx - half*768; int cin = r>>4, d = r&15;
      wreg[idx] = (half ? kW : qW)[(layer*16+d)*48 + cin];
    }
    if (tid < 32) wreg[1536+tid] = (tid<16) ? qb[layer*16+tid] : kb[layer*16+tid-16];
    for (int idx = tid; idx < 2048; idx += NT){
      int c = idx>>5, o = idx&31;
      wreg[1568+idx] = mW[(layer*32+o)*64 + c];
    }
    if (tid < 32){
      wreg[3616+tid] = mb[layer*32+tid];
      float sc = bng[layer*32+tid] * rsqrtf(bnv[layer*32+tid] + 1e-5f);
      wreg[3648+tid] = sc;
      wreg[3680+tid] = bnb[layer*32+tid] - bnm[layer*32+tid]*sc;
    }
  }

  // ---- phase 1b: skip contribution (only last time index) -------------------
  if (last_t && n < NN){
    float* skp = g_skip + b*256*NN + n;
    const float4* gxv = (const float4*)(s_gx + n*36);
    #pragma unroll 1
    for (int og=0; og<4; og++){
      int ot = 4*h + og;
      float acc[32];
      #pragma unroll
      for (int j=0;j<32;j++) acc[j] = skb[layer*256 + ot*32 + j];
      #pragma unroll 2
      for (int ci4=0; ci4<8; ci4++){
        float4 g4 = gxv[ci4];
        #pragma unroll
        for (int jj=0; jj<4; jj++){
          float xv = (jj==0)?g4.x:(jj==1)?g4.y:(jj==2)?g4.z:g4.w;
          const float4* wv = (const float4*)(s_swt + (ci4*4+jj)*256 + ot*32);
          #pragma unroll
          for (int j4=0;j4<8;j4++){
            float4 w = wv[j4];
            acc[4*j4+0]=fmaf(w.x,xv,acc[4*j4+0]); acc[4*j4+1]=fmaf(w.y,xv,acc[4*j4+1]);
            acc[4*j4+2]=fmaf(w.z,xv,acc[4*j4+2]); acc[4*j4+3]=fmaf(w.w,xv,acc[4*j4+3]);
          }
        }
      }
      #pragma unroll
      for (int j=0;j<32;j++) skp[(ot*32+j)*NN] += acc[j];
    }
  }
  if (!do_att) return;
  __syncthreads();

  // ---- phase 2: h=0 -> q (log2e/4 folded), h=1 -> k (packed) ----------------
  if (n < NN){
    ull a2[8];
    const float* wb = wreg + 768*h;
    {
      const ulonglong2* bp2 = (const ulonglong2*)(wreg + 1536 + 16*h);
      #pragma unroll
      for (int p=0;p<4;p++){ ulonglong2 v=bp2[p]; a2[2*p]=v.x; a2[2*p+1]=v.y; }
    }
    const float4* gxv = (const float4*)(s_gx + n*36);
    #pragma unroll 2
    for (int ci4=0; ci4<8; ci4++){
      float4 g4 = gxv[ci4];
      #pragma unroll
      for (int jj=0; jj<4; jj++){
        float xv = (jj==0)?g4.x:(jj==1)?g4.y:(jj==2)?g4.z:g4.w;
        ull xv2 = pack2(xv,xv);
        const ulonglong2* wv = (const ulonglong2*)(wb + (ci4*4+jj)*16);
        ulonglong2 wA=wv[0], wB=wv[1], wC=wv[2], wD=wv[3];
        a2[0]=fma2(xv2,wA.x,a2[0]); a2[1]=fma2(xv2,wA.y,a2[1]);
        a2[2]=fma2(xv2,wB.x,a2[2]); a2[3]=fma2(xv2,wB.y,a2[3]);
        a2[4]=fma2(xv2,wC.x,a2[4]); a2[5]=fma2(xv2,wC.y,a2[5]);
        a2[6]=fma2(xv2,wD.x,a2[6]); a2[7]=fma2(xv2,wD.y,a2[7]);
      }
    }
    #pragma unroll 4
    for (int e=0; e<16; e++){
      float xv = emb[e*NN+n];
      ull xv2 = pack2(xv,xv);
      const ulonglong2* wv = (const ulonglong2*)(wb + (32+e)*16);
      ulonglong2 wA=wv[0], wB=wv[1], wC=wv[2], wD=wv[3];
      a2[0]=fma2(xv2,wA.x,a2[0]); a2[1]=fma2(xv2,wA.y,a2[1]);
      a2[2]=fma2(xv2,wB.x,a2[2]); a2[3]=fma2(xv2,wB.y,a2[3]);
      a2[4]=fma2(xv2,wC.x,a2[4]); a2[5]=fma2(xv2,wC.y,a2[5]);
      a2[6]=fma2(xv2,wD.x,a2[6]); a2[7]=fma2(xv2,wD.y,a2[7]);
    }
    if (h == 0){
      ull qsc2 = pack2(0.36067376f, 0.36067376f);
      ull* qp = (ull*)(s_q + n*20);
      #pragma unroll
      for (int p=0;p<8;p++) qp[p] = mul2(a2[p], qsc2);
    } else {
      ull* kp = (ull*)(s_k + n*20);
      #pragma unroll
      for (int p=0;p<8;p++) kp[p] = a2[p];
    }
  }
  __syncthreads();

  // ---- phase 3: scores ONCE -> g_sc[m*328+c]; 2-acc online LSE --------------
  if (n < NN){
    ull qq[8];
    {
      const ulonglong2* qp = (const ulonglong2*)(s_q + n*20);
      #pragma unroll
      for (int p=0;p<4;p++){ ulonglong2 v=qp[p]; qq[2*p]=v.x; qq[2*p+1]=v.y; }
    }
    float* srow = g_sc + tile*SCT + (size_t)n*328;
    const int c0 = h ? 164 : 0;
    const int nvec = h ? 40 : 41;
    float mxE = -1e30f, ZE = 0.f, mxO = -1e30f, ZO = 0.f;
    #pragma unroll 1
    for (int v=0; v<nvec; v++){
      int c = c0 + 4*v;
      float s0 = dotqk(qq, s_k + (c+0)*20);
      float s1 = dotqk(qq, s_k + (c+1)*20);
      float s2 = dotqk(qq, s_k + (c+2)*20);
      float s3 = dotqk(qq, s_k + (c+3)*20);
      *(float4*)(srow + c) = make_float4(s0,s1,s2,s3);
      float nm;
      nm = fmaxf(mxE, s0); ZE = fmaf(ZE, ex2_(mxE-nm), ex2_(s0-nm)); mxE = nm;
      nm = fmaxf(mxO, s1); ZO = fmaf(ZO, ex2_(mxO-nm), ex2_(s1-nm)); mxO = nm;
      nm = fmaxf(mxE, s2); ZE = fmaf(ZE, ex2_(mxE-nm), ex2_(s2-nm)); mxE = nm;
      nm = fmaxf(mxO, s3); ZO = fmaf(ZO, ex2_(mxO-nm), ex2_(s3-nm)); mxO = nm;
    }
    if (h){
      float s0 = dotqk(qq, s_k + 324*20);
      srow[324] = s0;
      float nm = fmaxf(mxE, s0); ZE = fmaf(ZE, ex2_(mxE-nm), ex2_(s0-nm)); mxE = nm;
    }
    float mx = fmaxf(mxE, mxO);
    float Z  = ZE*ex2_(mxE-mx) + ZO*ex2_(mxO-mx);
    s_mxp[h*352+n] = mx;
    s_zp [h*352+n] = Z;
  }
  __syncthreads();
  if (h == 0 && n < NN){
    float mx0 = s_mxp[n], mx1 = s_mxp[352+n];
    float mx  = fmaxf(mx0, mx1);
    float Z   = s_zp[n]*ex2_(mx0-mx) + s_zp[352+n]*ex2_(mx1-mx);
    s_row[n]  = mx + lg2_(Z);
  }
  __syncthreads();

  // ---- phase 4: weighted sum from stored scores (clean loop, no guards) -----
  const int warp = tid >> 5, lane = tid & 31;
  const int bmh = warp & 1;
  const int bp  = (warp >> 1)*16 + (lane >> 1);   // 0..175
  const int bch = lane & 1;
  const int j1  = 2*bp, j2 = 2*bp + 1;

  ull xaA[8], xaB[8];
  #pragma unroll
  for (int p=0;p<8;p++){ xaA[p]=0ULL; xaB[p]=0ULL; }
  {
    const int mbase  = bmh ? 163 : 0;
    const int mcount = bmh ? 162 : 163;   // m=325 invalid -> simply dropped
    const float* sp2 = g_sc + tile*SCT + (size_t)mbase*328 + j1;
    #pragma unroll 8
    for (int i=0; i<mcount; i++){
      int m = mbase + i;
      float2 sc = *(const float2*)(sp2 + (size_t)i*328);
      float rw = s_row[m];
      float w1 = ex2_(sc.x - rw), w2 = ex2_(sc.y - rw);
      ull w12 = pack2(w1,w1), w22 = pack2(w2,w2);
      const ulonglong2* gv = (const ulonglong2*)(s_gx + m*36 + 16*bch);
      ulonglong2 gA=gv[0], gB=gv[1], gC=gv[2], gD=gv[3];
      xaA[0]=fma2(w12,gA.x,xaA[0]); xaA[1]=fma2(w12,gA.y,xaA[1]);
      xaA[2]=fma2(w12,gB.x,xaA[2]); xaA[3]=fma2(w12,gB.y,xaA[3]);
      xaA[4]=fma2(w12,gC.x,xaA[4]); xaA[5]=fma2(w12,gC.y,xaA[5]);
      xaA[6]=fma2(w12,gD.x,xaA[6]); xaA[7]=fma2(w12,gD.y,xaA[7]);
      xaB[0]=fma2(w22,gA.x,xaB[0]); xaB[1]=fma2(w22,gA.y,xaB[1]);
      xaB[2]=fma2(w22,gB.x,xaB[2]); xaB[3]=fma2(w22,gB.y,xaB[3]);
      xaB[4]=fma2(w22,gC.x,xaB[4]); xaB[5]=fma2(w22,gC.y,xaB[5]);
      xaB[6]=fma2(w22,gD.x,xaB[6]); xaB[7]=fma2(w22,gD.y,xaB[7]);
    }
  }
  __syncthreads();                  // attention reads of s_q/s_k region done
  if (bmh == 0 && j1 < NN){
    ulonglong2* xp1 = (ulonglong2*)(s_xa + j1*36 + 16*bch);
    xp1[0]=make_ulonglong2(xaA[0],xaA[1]); xp1[1]=make_ulonglong2(xaA[2],xaA[3]);
    xp1[2]=make_ulonglong2(xaA[4],xaA[5]); xp1[3]=make_ulonglong2(xaA[6],xaA[7]);
    if (j2 < NN){
      ulonglong2* xp2 = (ulonglong2*)(s_xa + j2*36 + 16*bch);
      xp2[0]=make_ulonglong2(xaB[0],xaB[1]); xp2[1]=make_ulonglong2(xaB[2],xaB[3]);
      xp2[2]=make_ulonglong2(xaB[4],xaB[5]); xp2[3]=make_ulonglong2(xaB[6],xaB[7]);
    }
  }
  __syncthreads();
  if (bmh == 1 && j1 < NN){
    ull* xp1 = (ull*)(s_xa + j1*36 + 16*bch);
    #pragma unroll
    for (int p=0;p<8;p++) xp1[p] = add2(xp1[p], xaA[p]);
    if (j2 < NN){
      ull* xp2 = (ull*)(s_xa + j2*36 + 16*bch);
      #pragma unroll
      for (int p=0;p<8;p++) xp2[p] = add2(xp2[p], xaB[p]);
    }
  }
  __syncthreads();

  // ---- phase 5: mlp (packed) + residual + BN ---------------------------------
  if (n < NN){
    ull o2[8];
    {
      const ulonglong2* bp2 = (const ulonglong2*)(wreg + 3616 + 16*h);
      #pragma unroll
      for (int p=0;p<4;p++){ ulonglong2 v=bp2[p]; o2[2*p]=v.x; o2[2*p+1]=v.y; }
    }
    const float4* gxv = (const float4*)(s_gx + n*36);
    const float4* xav = (const float4*)(s_xa + n*36);
    #pragma unroll 2
    for (int ci4=0; ci4<8; ci4++){
      float4 g4 = gxv[ci4];
      #pragma unroll
      for (int jj=0; jj<4; jj++){
        float xv = (jj==0)?g4.x:(jj==1)?g4.y:(jj==2)?g4.z:g4.w;
        ull xv2 = pack2(xv,xv);
        const ulonglong2* wv = (const ulonglong2*)(wreg + 1568 + (ci4*4+jj)*32 + 16*h);
        ulonglong2 wA=wv[0], wB=wv[1];
        o2[0]=fma2(xv2,wA.x,o2[0]); o2[1]=fma2(xv2,wA.y,o2[1]);
        o2[2]=fma2(xv2,wB.x,o2[2]); o2[3]=fma2(xv2,wB.y,o2[3]);
        wA=wv[2]; wB=wv[3];
        o2[4]=fma2(xv2,wA.x,o2[4]); o2[5]=fma2(xv2,wA.y,o2[5]);
        o2[6]=fma2(xv2,wB.x,o2[6]); o2[7]=fma2(xv2,wB.y,o2[7]);
      }
    }
    #pragma unroll 2
    for (int ci4=0; ci4<8; ci4++){
      float4 g4 = xav[ci4];
      #pragma unroll
      for (int jj=0; jj<4; jj++){
        float xv = (jj==0)?g4.x:(jj==1)?g4.y:(jj==2)?g4.z:g4.w;
        ull xv2 = pack2(xv,xv);
        const ulonglong2* wv = (const ulonglong2*)(wreg + 1568 + (32+ci4*4+jj)*32 + 16*h);
        ulonglong2 wA=wv[0], wB=wv[1];
        o2[0]=fma2(xv2,wA.x,o2[0]); o2[1]=fma2(xv2,wA.y,o2[1]);
        o2[2]=fma2(xv2,wB.x,o2[2]); o2[3]=fma2(xv2,wB.y,o2[3]);
        wA=wv[2]; wB=wv[3];
        o2[4]=fma2(xv2,wA.x,o2[4]); o2[5]=fma2(xv2,wA.y,o2[5]);
        o2[6]=fma2(xv2,wB.x,o2[6]); o2[7]=fma2(xv2,wB.y,o2[7]);
      }
    }
    const float* rin = Xin + base_in + dil*CNN + n;
    float* outp = Xout + base_in + n;
    #pragma unroll
    for (int p=0; p<8; p++){
      float va, vb; unpack2(o2[p], va, vb);
      int c0 = 16*h + 2*p, c1 = c0 + 1;
      float v0 = va + rin[c0*NN];
      float v1 = vb + rin[c1*NN];
      outp[c0*NN] = fmaf(v0, wreg[3648+c0], wreg[3680+c0]);
      outp[c1*NN] = fmaf(v1, wreg[3648+c1], wreg[3680+c1]);
    }
  }
}

// ---- head: relu(skip) -> relu(512) -> 12 ------------------------------------
#define H_SS 0
#define H_W1 16384
#define H_H  32832
#define H_W2 37184
#define H_B1 43328
#define HEAD_SMEM_BYTES (43840*4)

__global__ __launch_bounds__(256,1) void head_kernel(
    const float* __restrict__ w1, const float* __restrict__ b1,
    const float* __restrict__ w2, const float* __restrict__ b2,
    float* __restrict__ out)
{
  extern __shared__ __align__(16) float sm[];
  float* s_s = sm + H_SS;   // [256][64]
  float* w1s = sm + H_W1;   // [64][257]
  float* h_s = sm + H_H;    // [64][68]
  float* w2t = sm + H_W2;   // [512][12]
  float* b1s = sm + H_B1;   // [512]
  const int tid = threadIdx.x;
  const int p0 = blockIdx.x*64;

  for (int idx = tid; idx < 16384; idx += 256){
    int c = idx>>6, j = idx&63, p = p0 + j;
    int b = p/NN, nn = p - b*NN;
    s_s[idx] = fmaxf(g_skip[(b*256+c)*NN + nn], 0.f);
  }
  for (int idx = tid; idx < 6144; idx += 256){
    int o = idx/12, oo = idx - o*12;
    w2t[idx] = w2[oo*512 + o];
  }
  for (int idx = tid; idx < 512; idx += 256) b1s[idx] = b1[idx];

  const int op  = tid & 63, jg = tid >> 6;
  const int oo  = tid % 12, j0 = (tid/12)*4;
  float accO[4] = {0.f,0.f,0.f,0.f};

  for (int ot = 0; ot < 8; ot++){
    __syncthreads();
    for (int idx = tid; idx < 16384; idx += 256){
      int o = idx>>8, c = idx&255;
      w1s[o*257+c] = w1[(ot*64+o)*256 + c];
    }
    __syncthreads();
    {
      float acc[16];
      float bv = b1s[ot*64+op];
      #pragma unroll
      for (int k=0;k<16;k++) acc[k]=bv;
      #pragma unroll 2
      for (int c=0; c<256; c++){
        float w = w1s[op*257+c];
        const float4* sp = (const float4*)(s_s + c*64 + jg*16);
        #pragma unroll
        for (int k4=0;k4<4;k4++){
          float4 s4 = sp[k4];
          acc[4*k4+0]=fmaf(w,s4.x,acc[4*k4+0]); acc[4*k4+1]=fmaf(w,s4.y,acc[4*k4+1]);
          acc[4*k4+2]=fmaf(w,s4.z,acc[4*k4+2]); acc[4*k4+3]=fmaf(w,s4.w,acc[4*k4+3]);
        }
      }
      float4* hp = (float4*)(h_s + op*68 + jg*16);
      #pragma unroll
      for (int k4=0;k4<4;k4++)
        hp[k4] = make_float4(fmaxf(acc[4*k4+0],0.f), fmaxf(acc[4*k4+1],0.f),
                             fmaxf(acc[4*k4+2],0.f), fmaxf(acc[4*k4+3],0.f));
    }
    __syncthreads();
    if (tid < 192){
      #pragma unroll 4
      for (int o=0; o<64; o++){
        float w = w2t[(ot*64+o)*12 + oo];
        const float4* hp = (const float4*)(h_s + o*68 + j0);
        float4 h4 = hp[0];
        accO[0]=fmaf(w,h4.x,accO[0]); accO[1]=fmaf(w,h4.y,accO[1]);
        accO[2]=fmaf(w,h4.z,accO[2]); accO[3]=fmaf(w,h4.w,accO[3]);
      }
    }
  }
  if (tid < 192){
    float bb = b2[oo];
    #pragma unroll
    for (int k=0;k<4;k++){
      int p = p0 + j0 + k;
      int b = p/NN, nn = p - b*NN;
      out[(b*12+oo)*NN + nn] = accO[k] + bb;
    }
  }
}

// ---- host -------------------------------------------------------------------
extern "C" void kernel_launch(void* const* d_in, const int* in_sizes, int n_in,
                              void* d_out, int out_size){
  const float* x    = (const float*)d_in[0];
  const float* emb  = (const float*)d_in[1];
  const float* stW  = (const float*)d_in[2];
  const float* stb  = (const float*)d_in[3];
  const float* fW   = (const float*)d_in[4];
  const float* fb   = (const float*)d_in[5];
  const float* gW   = (const float*)d_in[6];
  const float* gb   = (const float*)d_in[7];
  const float* skW  = (const float*)d_in[8];
  const float* skb  = (const float*)d_in[9];
  const float* qW   = (const float*)d_in[10];
  const float* qb   = (const float*)d_in[11];
  const float* kW   = (const float*)d_in[12];
  const float* kb   = (const float*)d_in[13];
  const float* mW   = (const float*)d_in[14];
  const float* mb   = (const float*)d_in[15];
  const float* bng  = (const float*)d_in[16];
  const float* bnb  = (const float*)d_in[17];
  const float* bnm  = (const float*)d_in[18];
  const float* bnv  = (const float*)d_in[19];
  const float* e1W  = (const float*)d_in[20];
  const float* e1b  = (const float*)d_in[21];
  const float* e2W  = (const float*)d_in[22];
  const float* e2b  = (const float*)d_in[23];
  float* out = (float*)d_out;

  cudaFuncSetAttribute(layer_kernel, cudaFuncAttributeMaxDynamicSharedMemorySize, LAYER_SMEM_BYTES);
  cudaFuncSetAttribute(head_kernel,  cudaFuncAttributeMaxDynamicSharedMemorySize, HEAD_SMEM_BYTES);

  start_kernel<<<54600, 256>>>(x, stW, stb);

  const int dil[8]  = {1,2,1,2,1,2,1,2};
  const int Tout[8] = {12,10,9,7,6,4,3,1};
  for (int i = 0; i < 8; i++){
    layer_kernel<<<dim3(Tout[i], 64), NT, LAYER_SMEM_BYTES>>>(
        i, dil[i], (i != 7) ? 1 : 0, i & 1,
        fW, fb, gW, gb, skW, skb, qW, qb, kW, kb, mW, mb,
        bng, bnb, bnm, bnv, emb);
  }

  head_kernel<<<325, 256, HEAD_SMEM_BYTES>>>(e1W, e1b, e2W, e2b, out);
}

// round 15
// speedup vs baseline: 1.1336x; 1.0675x over previous
#include <cuda_runtime.h>

#define NN 325
#define CNN (32*NN)
#define NT 704          // 2 threads per node slot for phases 1/2/5

typedef unsigned long long ull;

static __device__ float g_X0[64*13*CNN];
static __device__ float g_X1[64*13*CNN];
static __device__ float g_skip[64*256*NN];
#define SCT (328*328)
static __device__ float g_sc[256u*SCT];   // per-SM score scratch (slot = %smid), L2-resident

// ---- MUFU helpers (SFU pipe; rel err ~1e-6) ---------------------------------
__device__ __forceinline__ float ex2_(float x){ float r; asm("ex2.approx.f32 %0,%1;":"=f"(r):"f"(x)); return r; }
__device__ __forceinline__ float lg2_(float x){ float r; asm("lg2.approx.f32 %0,%1;":"=f"(r):"f"(x)); return r; }
__device__ __forceinline__ float rcp_(float x){ float r; asm("rcp.approx.f32 %0,%1;":"=f"(r):"f"(x)); return r; }

// ---- packed f32x2 helpers (sm_100+) -----------------------------------------
__device__ __forceinline__ ull pack2(float lo, float hi){
  ull r; asm("mov.b64 %0, {%1,%2};" : "=l"(r) : "f"(lo), "f"(hi)); return r;
}
__device__ __forceinline__ void unpack2(ull v, float& lo, float& hi){
  asm("mov.b64 {%0,%1}, %2;" : "=f"(lo), "=f"(hi) : "l"(v));
}
__device__ __forceinline__ ull fma2(ull a, ull b, ull c){
  ull d; asm("fma.rn.f32x2 %0, %1, %2, %3;" : "=l"(d) : "l"(a), "l"(b), "l"(c)); return d;
}
__device__ __forceinline__ ull mul2(ull a, ull b){
  ull d; asm("mul.rn.f32x2 %0, %1, %2;" : "=l"(d) : "l"(a), "l"(b)); return d;
}
__device__ __forceinline__ ull add2(ull a, ull b){
  ull d; asm("add.rn.f32x2 %0, %1, %2;" : "=l"(d) : "l"(a), "l"(b)); return d;
}

__device__ __forceinline__ float dotqk(const ull* qq, const float* kp_f){
  const ulonglong2* kp = (const ulonglong2*)kp_f;
  ulonglong2 kA=kp[0], kB=kp[1], kC=kp[2], kD=kp[3];
  ull d0 = mul2(qq[0],kA.x); d0=fma2(qq[1],kA.y,d0); d0=fma2(qq[2],kB.x,d0); d0=fma2(qq[3],kB.y,d0);
  ull d1 = mul2(qq[4],kC.x); d1=fma2(qq[5],kC.y,d1); d1=fma2(qq[6],kD.x,d1); d1=fma2(qq[7],kD.y,d1);
  float s0,s1,s2,s3; unpack2(d0,s0,s1); unpack2(d1,s2,s3);
  return (s0+s1)+(s2+s3);
}

// ---- start conv + skip zero -------------------------------------------------
__global__ __launch_bounds__(256) void start_kernel(const float* __restrict__ x,
                                                    const float* __restrict__ sW,
                                                    const float* __restrict__ sb){
  int i = blockIdx.x*256 + threadIdx.x;
  const int tot = 64*13*CNN;
  if (i < tot){
    int n = i % NN; int r = i / NN;
    int c = r & 31; r >>= 5;
    int t = r % 13; int b = r / 13;
    float v0 = x[((b*2+0)*NN + n)*13 + t];
    float v1 = x[((b*2+1)*NN + n)*13 + t];
    g_X0[i] = fmaf(sW[c*2], v0, fmaf(sW[c*2+1], v1, sb[c]));
  } else {
    int j = i - tot;
    if (j < 64*256*NN) g_skip[j] = 0.f;
  }
}

// ---- fused layer kernel -----------------------------------------------------
#define OFF_K     7040
#define OFF_MXP   14080
#define OFF_ZP    14784
#define OFF_GX    15488    // [352][36]
#define OFF_W     28160    // staged weights (max 4192)
#define OFF_ROW   32352    // [352]
#define LAYER_SMEM_BYTES (32704*4)

__global__ __launch_bounds__(NT,1) void layer_kernel(
    int layer, int dil, int do_att, int parity,
    const float* __restrict__ fW,  const float* __restrict__ fb,
    const float* __restrict__ gW,  const float* __restrict__ gb,
    const float* __restrict__ skW, const float* __restrict__ skb,
    const float* __restrict__ qW,  const float* __restrict__ qb,
    const float* __restrict__ kW,  const float* __restrict__ kb,
    const float* __restrict__ mW,  const float* __restrict__ mb,
    const float* __restrict__ bng, const float* __restrict__ bnb,
    const float* __restrict__ bnm, const float* __restrict__ bnv,
    const float* __restrict__ emb)
{
  extern __shared__ __align__(16) float sm[];
  const float* __restrict__ Xin  = parity ? g_X1 : g_X0;
  float* __restrict__       Xout = parity ? g_X0 : g_X1;
  const int t = blockIdx.x, b = blockIdx.y, tid = threadIdx.x;
  const int Tout = gridDim.x;
  const int n = tid % 352;
  const int h = tid / 352;
  const int last_t = (t == Tout-1);

  // SM-resident scratch slot: occupancy is structurally 1 block/SM (regfile),
  // so %smid uniquely identifies the resident block; successive blocks on the
  // same SM overwrite the same L2-hot lines (no cold DRAM writeback).
  unsigned int smid_; asm("mov.u32 %0, %%smid;" : "=r"(smid_));
  const size_t tile = (size_t)(smid_ & 255u);

  float* s_swt = sm;               // [32][256] (phase 0..1b)
  float* s_q   = sm;               // [352][20] (phases 2-3)
  float* s_k   = sm + OFF_K;       // [352][20]
  float* s_mxp = sm + OFF_MXP;     // [2][352]
  float* s_zp  = sm + OFF_ZP;      // [2][352]
  float* s_xa  = sm;               // [352][36] (after xa loop)
  float* s_gx  = sm + OFF_GX;      // [352][36]
  float* wreg  = sm + OFF_W;
  float* s_row = sm + OFF_ROW;

  // ---- phase 0: stage gated weights [ci][kind f0,f1,g0,g1][co] + biases -----
  for (int idx = tid; idx < 4096; idx += NT){
    int ci = idx>>7, r = idx&127, kind = r>>5, co = r&31;
    const float* src = (kind < 2) ? fW : gW;
    wreg[idx] = src[((layer*32+co)*32+ci)*2 + (kind & 1)];
  }
  if (tid < 64) wreg[4096+tid] = (tid<32) ? fb[layer*32+tid] : gb[layer*32+tid-32];
  if (last_t){
    for (int idx = tid; idx < 8192; idx += NT){
      int ci = idx>>8, o = idx&255;
      s_swt[idx] = skW[(layer*256+o)*32 + ci];
    }
  }
  __syncthreads();

  // ---- phase 1: gated conv (packed f32x2), half the channels per thread -----
  const int base_in = (b*13 + t)*CNN;
  if (n < NN){
    const float* xin = Xin + base_in + n;
    const float* xrn = xin + dil*CNN;
    ull f2[8], g2[8];
    {
      const ulonglong2* fbp = (const ulonglong2*)(wreg + 4096 + 16*h);
      const ulonglong2* gbp = (const ulonglong2*)(wreg + 4128 + 16*h);
      #pragma unroll
      for (int p=0;p<4;p++){ ulonglong2 a=fbp[p], c=gbp[p]; f2[2*p]=a.x; f2[2*p+1]=a.y; g2[2*p]=c.x; g2[2*p+1]=c.y; }
    }
    #pragma unroll 4
    for (int ci=0; ci<32; ci++){
      float xl = xin[ci*NN], xr = xrn[ci*NN];
      ull xl2 = pack2(xl,xl), xr2 = pack2(xr,xr);
      const ulonglong2* p0 = (const ulonglong2*)(wreg + ci*128      + 16*h);
      const ulonglong2* p1 = (const ulonglong2*)(wreg + ci*128 + 32 + 16*h);
      const ulonglong2* p2 = (const ulonglong2*)(wreg + ci*128 + 64 + 16*h);
      const ulonglong2* p3 = (const ulonglong2*)(wreg + ci*128 + 96 + 16*h);
      #pragma unroll
      for (int p4=0;p4<4;p4++){
        ulonglong2 a=p0[p4], bb=p1[p4], c=p2[p4], d=p3[p4];
        f2[2*p4]   = fma2(xl2, a.x,  f2[2*p4]);   f2[2*p4+1] = fma2(xl2, a.y,  f2[2*p4+1]);
        f2[2*p4]   = fma2(xr2, bb.x, f2[2*p4]);   f2[2*p4+1] = fma2(xr2, bb.y, f2[2*p4+1]);
        g2[2*p4]   = fma2(xl2, c.x,  g2[2*p4]);   g2[2*p4+1] = fma2(xl2, c.y,  g2[2*p4+1]);
        g2[2*p4]   = fma2(xr2, d.x,  g2[2*p4]);   g2[2*p4+1] = fma2(xr2, d.y,  g2[2*p4+1]);
      }
    }
    #pragma unroll
    for (int p=0;p<8;p++){
      float fa,fb2, ga,gb2;
      unpack2(f2[p], fa, fb2); unpack2(g2[p], ga, gb2);
      float efa = ex2_(-2.88539008f*fa), ega = ex2_(-1.44269504f*ga);
      float efb = ex2_(-2.88539008f*fb2), egb = ex2_(-1.44269504f*gb2);
      s_gx[n*36 + 16*h + 2*p]   = (1.f - efa) * rcp_((1.f + efa)*(1.f + ega));
      s_gx[n*36 + 16*h + 2*p+1] = (1.f - efb) * rcp_((1.f + efb)*(1.f + egb));
    }
  }
  __syncthreads();

  // ---- stage attention-phase weights ----------------------------------------
  if (do_att){
    for (int idx = tid; idx < 1536; idx += NT){
      int half = (idx >= 768) ? 1 : 0;
      int r = idx - half*768; int cin = r>>4, d = r&15;
      wreg[idx] = (half ? kW : qW)[(layer*16+d)*48 + cin];
    }
    if (tid < 32) wreg[1536+tid] = (tid<16) ? qb[layer*16+tid] : kb[layer*16+tid-16];
    for (int idx = tid; idx < 2048; idx += NT){
      int c = idx>>5, o = idx&31;
      wreg[1568+idx] = mW[(layer*32+o)*64 + c];
    }
    if (tid < 32){
      wreg[3616+tid] = mb[layer*32+tid];
      float sc = bng[layer*32+tid] * rsqrtf(bnv[layer*32+tid] + 1e-5f);
      wreg[3648+tid] = sc;
      wreg[3680+tid] = bnb[layer*32+tid] - bnm[layer*32+tid]*sc;
    }
  }

  // ---- phase 1b: skip contribution (only last time index) -------------------
  if (last_t && n < NN){
    float* skp = g_skip + b*256*NN + n;
    const float4* gxv = (const float4*)(s_gx + n*36);
    #pragma unroll 1
    for (int og=0; og<4; og++){
      int ot = 4*h + og;
      float acc[32];
      #pragma unroll
      for (int j=0;j<32;j++) acc[j] = skb[layer*256 + ot*32 + j];
      #pragma unroll 2
      for (int ci4=0; ci4<8; ci4++){
        float4 g4 = gxv[ci4];
        #pragma unroll
        for (int jj=0; jj<4; jj++){
          float xv = (jj==0)?g4.x:(jj==1)?g4.y:(jj==2)?g4.z:g4.w;
          const float4* wv = (const float4*)(s_swt + (ci4*4+jj)*256 + ot*32);
          #pragma unroll
          for (int j4=0;j4<8;j4++){
            float4 w = wv[j4];
            acc[4*j4+0]=fmaf(w.x,xv,acc[4*j4+0]); acc[4*j4+1]=fmaf(w.y,xv,acc[4*j4+1]);
            acc[4*j4+2]=fmaf(w.z,xv,acc[4*j4+2]); acc[4*j4+3]=fmaf(w.w,xv,acc[4*j4+3]);
          }
        }
      }
      #pragma unroll
      for (int j=0;j<32;j++) skp[(ot*32+j)*NN] += acc[j];
    }
  }
  if (!do_att) return;
  __syncthreads();

  // ---- phase 2: h=0 -> q (log2e/4 folded), h=1 -> k (packed) ----------------
  if (n < NN){
    ull a2[8];
    const float* wb = wreg + 768*h;
    {
      const ulonglong2* bp2 = (const ulonglong2*)(wreg + 1536 + 16*h);
      #pragma unroll
      for (int p=0;p<4;p++){ ulonglong2 v=bp2[p]; a2[2*p]=v.x; a2[2*p+1]=v.y; }
    }
    const float4* gxv = (const float4*)(s_gx + n*36);
    #pragma unroll 2
    for (int ci4=0; ci4<8; ci4++){
      float4 g4 = gxv[ci4];
      #pragma unroll
      for (int jj=0; jj<4; jj++){
        float xv = (jj==0)?g4.x:(jj==1)?g4.y:(jj==2)?g4.z:g4.w;
        ull xv2 = pack2(xv,xv);
        const ulonglong2* wv = (const ulonglong2*)(wb + (ci4*4+jj)*16);
        ulonglong2 wA=wv[0], wB=wv[1], wC=wv[2], wD=wv[3];
        a2[0]=fma2(xv2,wA.x,a2[0]); a2[1]=fma2(xv2,wA.y,a2[1]);
        a2[2]=fma2(xv2,wB.x,a2[2]); a2[3]=fma2(xv2,wB.y,a2[3]);
        a2[4]=fma2(xv2,wC.x,a2[4]); a2[5]=fma2(xv2,wC.y,a2[5]);
        a2[6]=fma2(xv2,wD.x,a2[6]); a2[7]=fma2(xv2,wD.y,a2[7]);
      }
    }
    #pragma unroll 4
    for (int e=0; e<16; e++){
      float xv = emb[e*NN+n];
      ull xv2 = pack2(xv,xv);
      const ulonglong2* wv = (const ulonglong2*)(wb + (32+e)*16);
      ulonglong2 wA=wv[0], wB=wv[1], wC=wv[2], wD=wv[3];
      a2[0]=fma2(xv2,wA.x,a2[0]); a2[1]=fma2(xv2,wA.y,a2[1]);
      a2[2]=fma2(xv2,wB.x,a2[2]); a2[3]=fma2(xv2,wB.y,a2[3]);
      a2[4]=fma2(xv2,wC.x,a2[4]); a2[5]=fma2(xv2,wC.y,a2[5]);
      a2[6]=fma2(xv2,wD.x,a2[6]); a2[7]=fma2(xv2,wD.y,a2[7]);
    }
    if (h == 0){
      ull qsc2 = pack2(0.36067376f, 0.36067376f);
      ull* qp = (ull*)(s_q + n*20);
      #pragma unroll
      for (int p=0;p<8;p++) qp[p] = mul2(a2[p], qsc2);
    } else {
      ull* kp = (ull*)(s_k + n*20);
      #pragma unroll
      for (int p=0;p<8;p++) kp[p] = a2[p];
    }
  }
  __syncthreads();

  // ---- phase 3: scores ONCE -> g_sc[m*328+c]; 2-acc online LSE --------------
  if (n < NN){
    ull qq[8];
    {
      const ulonglong2* qp = (const ulonglong2*)(s_q + n*20);
      #pragma unroll
      for (int p=0;p<4;p++){ ulonglong2 v=qp[p]; qq[2*p]=v.x; qq[2*p+1]=v.y; }
    }
    float* srow = g_sc + tile*SCT + (size_t)n*328;
    const int c0 = h ? 164 : 0;
    const int nvec = h ? 40 : 41;
    float mxE = -1e30f, ZE = 0.f, mxO = -1e30f, ZO = 0.f;
    #pragma unroll 1
    for (int v=0; v<nvec; v++){
      int c = c0 + 4*v;
      float s0 = dotqk(qq, s_k + (c+0)*20);
      float s1 = dotqk(qq, s_k + (c+1)*20);
      float s2 = dotqk(qq, s_k + (c+2)*20);
      float s3 = dotqk(qq, s_k + (c+3)*20);
      *(float4*)(srow + c) = make_float4(s0,s1,s2,s3);
      float nm;
      nm = fmaxf(mxE, s0); ZE = fmaf(ZE, ex2_(mxE-nm), ex2_(s0-nm)); mxE = nm;
      nm = fmaxf(mxO, s1); ZO = fmaf(ZO, ex2_(mxO-nm), ex2_(s1-nm)); mxO = nm;
      nm = fmaxf(mxE, s2); ZE = fmaf(ZE, ex2_(mxE-nm), ex2_(s2-nm)); mxE = nm;
      nm = fmaxf(mxO, s3); ZO = fmaf(ZO, ex2_(mxO-nm), ex2_(s3-nm)); mxO = nm;
    }
    if (h){
      float s0 = dotqk(qq, s_k + 324*20);
      srow[324] = s0;
      float nm = fmaxf(mxE, s0); ZE = fmaf(ZE, ex2_(mxE-nm), ex2_(s0-nm)); mxE = nm;
    }
    float mx = fmaxf(mxE, mxO);
    float Z  = ZE*ex2_(mxE-mx) + ZO*ex2_(mxO-mx);
    s_mxp[h*352+n] = mx;
    s_zp [h*352+n] = Z;
  }
  __syncthreads();
  if (h == 0 && n < NN){
    float mx0 = s_mxp[n], mx1 = s_mxp[352+n];
    float mx  = fmaxf(mx0, mx1);
    float Z   = s_zp[n]*ex2_(mx0-mx) + s_zp[352+n]*ex2_(mx1-mx);
    s_row[n]  = mx + lg2_(Z);
  }
  __syncthreads();

  // ---- phase 4: weighted sum from stored scores (clean loop, no guards) -----
  const int warp = tid >> 5, lane = tid & 31;
  const int bmh = warp & 1;
  const int bp  = (warp >> 1)*16 + (lane >> 1);   // 0..175
  const int bch = lane & 1;
  const int j1  = 2*bp, j2 = 2*bp + 1;

  ull xaA[8], xaB[8];
  #pragma unroll
  for (int p=0;p<8;p++){ xaA[p]=0ULL; xaB[p]=0ULL; }
  {
    const int mbase  = bmh ? 163 : 0;
    const int mcount = bmh ? 162 : 163;   // m=325 invalid -> simply dropped
    const float* sp2 = g_sc + tile*SCT + (size_t)mbase*328 + j1;
    #pragma unroll 8
    for (int i=0; i<mcount; i++){
      int m = mbase + i;
      float2 sc = *(const float2*)(sp2 + (size_t)i*328);
      float rw = s_row[m];
      float w1 = ex2_(sc.x - rw), w2 = ex2_(sc.y - rw);
      ull w12 = pack2(w1,w1), w22 = pack2(w2,w2);
      const ulonglong2* gv = (const ulonglong2*)(s_gx + m*36 + 16*bch);
      ulonglong2 gA=gv[0], gB=gv[1], gC=gv[2], gD=gv[3];
      xaA[0]=fma2(w12,gA.x,xaA[0]); xaA[1]=fma2(w12,gA.y,xaA[1]);
      xaA[2]=fma2(w12,gB.x,xaA[2]); xaA[3]=fma2(w12,gB.y,xaA[3]);
      xaA[4]=fma2(w12,gC.x,xaA[4]); xaA[5]=fma2(w12,gC.y,xaA[5]);
      xaA[6]=fma2(w12,gD.x,xaA[6]); xaA[7]=fma2(w12,gD.y,xaA[7]);
      xaB[0]=fma2(w22,gA.x,xaB[0]); xaB[1]=fma2(w22,gA.y,xaB[1]);
      xaB[2]=fma2(w22,gB.x,xaB[2]); xaB[3]=fma2(w22,gB.y,xaB[3]);
      xaB[4]=fma2(w22,gC.x,xaB[4]); xaB[5]=fma2(w22,gC.y,xaB[5]);
      xaB[6]=fma2(w22,gD.x,xaB[6]); xaB[7]=fma2(w22,gD.y,xaB[7]);
    }
  }
  __syncthreads();                  // attention reads of s_q/s_k region done
  if (bmh == 0 && j1 < NN){
    ulonglong2* xp1 = (ulonglong2*)(s_xa + j1*36 + 16*bch);
    xp1[0]=make_ulonglong2(xaA[0],xaA[1]); xp1[1]=make_ulonglong2(xaA[2],xaA[3]);
    xp1[2]=make_ulonglong2(xaA[4],xaA[5]); xp1[3]=make_ulonglong2(xaA[6],xaA[7]);
    if (j2 < NN){
      ulonglong2* xp2 = (ulonglong2*)(s_xa + j2*36 + 16*bch);
      xp2[0]=make_ulonglong2(xaB[0],xaB[1]); xp2[1]=make_ulonglong2(xaB[2],xaB[3]);
      xp2[2]=make_ulonglong2(xaB[4],xaB[5]); xp2[3]=make_ulonglong2(xaB[6],xaB[7]);
    }
  }
  __syncthreads();
  if (bmh == 1 && j1 < NN){
    ull* xp1 = (ull*)(s_xa + j1*36 + 16*bch);
    #pragma unroll
    for (int p=0;p<8;p++) xp1[p] = add2(xp1[p], xaA[p]);
    if (j2 < NN){
      ull* xp2 = (ull*)(s_xa + j2*36 + 16*bch);
      #pragma unroll
      for (int p=0;p<8;p++) xp2[p] = add2(xp2[p], xaB[p]);
    }
  }
  __syncthreads();

  // ---- phase 5: mlp (packed) + residual + BN ---------------------------------
  if (n < NN){
    ull o2[8];
    {
      const ulonglong2* bp2 = (const ulonglong2*)(wreg + 3616 + 16*h);
      #pragma unroll
      for (int p=0;p<4;p++){ ulonglong2 v=bp2[p]; o2[2*p]=v.x; o2[2*p+1]=v.y; }
    }
    const float4* gxv = (const float4*)(s_gx + n*36);
    const float4* xav = (const float4*)(s_xa + n*36);
    #pragma unroll 2
    for (int ci4=0; ci4<8; ci4++){
      float4 g4 = gxv[ci4];
      #pragma unroll
      for (int jj=0; jj<4; jj++){
        float xv = (jj==0)?g4.x:(jj==1)?g4.y:(jj==2)?g4.z:g4.w;
        ull xv2 = pack2(xv,xv);
        const ulonglong2* wv = (const ulonglong2*)(wreg + 1568 + (ci4*4+jj)*32 + 16*h);
        ulonglong2 wA=wv[0], wB=wv[1];
        o2[0]=fma2(xv2,wA.x,o2[0]); o2[1]=fma2(xv2,wA.y,o2[1]);
        o2[2]=fma2(xv2,wB.x,o2[2]); o2[3]=fma2(xv2,wB.y,o2[3]);
        wA=wv[2]; wB=wv[3];
        o2[4]=fma2(xv2,wA.x,o2[4]); o2[5]=fma2(xv2,wA.y,o2[5]);
        o2[6]=fma2(xv2,wB.x,o2[6]); o2[7]=fma2(xv2,wB.y,o2[7]);
      }
    }
    #pragma unroll 2
    for (int ci4=0; ci4<8; ci4++){
      float4 g4 = xav[ci4];
      #pragma unroll
      for (int jj=0; jj<4; jj++){
        float xv = (jj==0)?g4.x:(jj==1)?g4.y:(jj==2)?g4.z:g4.w;
        ull xv2 = pack2(xv,xv);
        const ulonglong2* wv = (const ulonglong2*)(wreg + 1568 + (32+ci4*4+jj)*32 + 16*h);
        ulonglong2 wA=wv[0], wB=wv[1];
        o2[0]=fma2(xv2,wA.x,o2[0]); o2[1]=fma2(xv2,wA.y,o2[1]);
        o2[2]=fma2(xv2,wB.x,o2[2]); o2[3]=fma2(xv2,wB.y,o2[3]);
        wA=wv[2]; wB=wv[3];
        o2[4]=fma2(xv2,wA.x,o2[4]); o2[5]=fma2(xv2,wA.y,o2[5]);
        o2[6]=fma2(xv2,wB.x,o2[6]); o2[7]=fma2(xv2,wB.y,o2[7]);
      }
    }
    const float* rin = Xin + base_in + dil*CNN + n;
    float* outp = Xout + base_in + n;
    #pragma unroll
    for (int p=0; p<8; p++){
      float va, vb; unpack2(o2[p], va, vb);
      int c0 = 16*h + 2*p, c1 = c0 + 1;
      float v0 = va + rin[c0*NN];
      float v1 = vb + rin[c1*NN];
      outp[c0*NN] = fmaf(v0, wreg[3648+c0], wreg[3680+c0]);
      outp[c1*NN] = fmaf(v1, wreg[3648+c1], wreg[3680+c1]);
    }
  }
}

// ---- head: relu(skip) -> relu(512) -> 12 ------------------------------------
#define H_SS 0
#define H_W1 16384
#define H_H  32832
#define H_W2 37184
#define H_B1 43328
#define HEAD_SMEM_BYTES (43840*4)

__global__ __launch_bounds__(256,1) void head_kernel(
    const float* __restrict__ w1, const float* __restrict__ b1,
    const float* __restrict__ w2, const float* __restrict__ b2,
    float* __restrict__ out)
{
  extern __shared__ __align__(16) float sm[];
  float* s_s = sm + H_SS;   // [256][64]
  float* w1s = sm + H_W1;   // [64][257]
  float* h_s = sm + H_H;    // [64][68]
  float* w2t = sm + H_W2;   // [512][12]
  float* b1s = sm + H_B1;   // [512]
  const int tid = threadIdx.x;
  const int p0 = blockIdx.x*64;

  for (int idx = tid; idx < 16384; idx += 256){
    int c = idx>>6, j = idx&63, p = p0 + j;
    int b = p/NN, nn = p - b*NN;
    s_s[idx] = fmaxf(g_skip[(b*256+c)*NN + nn], 0.f);
  }
  for (int idx = tid; idx < 6144; idx += 256){
    int o = idx/12, oo = idx - o*12;
    w2t[idx] = w2[oo*512 + o];
  }
  for (int idx = tid; idx < 512; idx += 256) b1s[idx] = b1[idx];

  const int op  = tid & 63, jg = tid >> 6;
  const int oo  = tid % 12, j0 = (tid/12)*4;
  float accO[4] = {0.f,0.f,0.f,0.f};

  for (int ot = 0; ot < 8; ot++){
    __syncthreads();
    for (int idx = tid; idx < 16384; idx += 256){
      int o = idx>>8, c = idx&255;
      w1s[o*257+c] = w1[(ot*64+o)*256 + c];
    }
    __syncthreads();
    {
      float acc[16];
      float bv = b1s[ot*64+op];
      #pragma unroll
      for (int k=0;k<16;k++) acc[k]=bv;
      #pragma unroll 2
      for (int c=0; c<256; c++){
        float w = w1s[op*257+c];
        const float4* sp = (const float4*)(s_s + c*64 + jg*16);
        #pragma unroll
        for (int k4=0;k4<4;k4++){
          float4 s4 = sp[k4];
          acc[4*k4+0]=fmaf(w,s4.x,acc[4*k4+0]); acc[4*k4+1]=fmaf(w,s4.y,acc[4*k4+1]);
          acc[4*k4+2]=fmaf(w,s4.z,acc[4*k4+2]); acc[4*k4+3]=fmaf(w,s4.w,acc[4*k4+3]);
        }
      }
      float4* hp = (float4*)(h_s + op*68 + jg*16);
      #pragma unroll
      for (int k4=0;k4<4;k4++)
        hp[k4] = make_float4(fmaxf(acc[4*k4+0],0.f), fmaxf(acc[4*k4+1],0.f),
                             fmaxf(acc[4*k4+2],0.f), fmaxf(acc[4*k4+3],0.f));
    }
    __syncthreads();
    if (tid < 192){
      #pragma unroll 4
      for (int o=0; o<64; o++){
        float w = w2t[(ot*64+o)*12 + oo];
        const float4* hp = (const float4*)(h_s + o*68 + j0);
        float4 h4 = hp[0];
        accO[0]=fmaf(w,h4.x,accO[0]); accO[1]=fmaf(w,h4.y,accO[1]);
        accO[2]=fmaf(w,h4.z,accO[2]); accO[3]=fmaf(w,h4.w,accO[3]);
      }
    }
  }
  if (tid < 192){
    float bb = b2[oo];
    #pragma unroll
    for (int k=0;k<4;k++){
      int p = p0 + j0 + k;
      int b = p/NN, nn = p - b*NN;
      out[(b*12+oo)*NN + nn] = accO[k] + bb;
    }
  }
}

// ---- host -------------------------------------------------------------------
extern "C" void kernel_launch(void* const* d_in, const int* in_sizes, int n_in,
                              void* d_out, int out_size){
  const float* x    = (const float*)d_in[0];
  const float* emb  = (const float*)d_in[1];
  const float* stW  = (const float*)d_in[2];
  const float* stb  = (const float*)d_in[3];
  const float* fW   = (const float*)d_in[4];
  const float* fb   = (const float*)d_in[5];
  const float* gW   = (const float*)d_in[6];
  const float* gb   = (const float*)d_in[7];
  const float* skW  = (const float*)d_in[8];
  const float* skb  = (const float*)d_in[9];
  const float* qW   = (const float*)d_in[10];
  const float* qb   = (const float*)d_in[11];
  const float* kW   = (const float*)d_in[12];
  const float* kb   = (const float*)d_in[13];
  const float* mW   = (const float*)d_in[14];
  const float* mb   = (const float*)d_in[15];
  const float* bng  = (const float*)d_in[16];
  const float* bnb  = (const float*)d_in[17];
  const float* bnm  = (const float*)d_in[18];
  const float* bnv  = (const float*)d_in[19];
  const float* e1W  = (const float*)d_in[20];
  const float* e1b  = (const float*)d_in[21];
  const float* e2W  = (const float*)d_in[22];
  const float* e2b  = (const float*)d_in[23];
  float* out = (float*)d_out;

  cudaFuncSetAttribute(layer_kernel, cudaFuncAttributeMaxDynamicSharedMemorySize, LAYER_SMEM_BYTES);
  cudaFuncSetAttribute(head_kernel,  cudaFuncAttributeMaxDynamicSharedMemorySize, HEAD_SMEM_BYTES);

  start_kernel<<<54600, 256>>>(x, stW, stb);

  const int dil[8]  = {1,2,1,2,1,2,1,2};
  const int Tout[8] = {12,10,9,7,6,4,3,1};
  for (int i = 0; i < 8; i++){
    layer_kernel<<<dim3(Tout[i], 64), NT, LAYER_SMEM_BYTES>>>(
        i, dil[i], (i != 7) ? 1 : 0, i & 1,
        fW, fb, gW, gb, skW, skb, qW, qb, kW, kb, mW, mb,
        bng, bnb, bnm, bnv, emb);
  }

  head_kernel<<<325, 256, HEAD_SMEM_BYTES>>>(e1W, e1b, e2W, e2b, out);
}

// round 16
// speedup vs baseline: 1.2726x; 1.1226x over previous
#include <cuda_runtime.h>

#define NN 325
#define CNN (32*NN)
#define NT 704          // 2 threads per node slot for phases 1/2/5

typedef unsigned long long ull;

static __device__ float g_X0[64*13*CNN];
static __device__ float g_X1[64*13*CNN];
static __device__ float g_skip[64*256*NN];
#define SCT (328*328)
static __device__ float g_sc[256u*SCT];   // per-block score scratch, L2-resident
static __device__ int   g_flag[8*832];    // per (layer, b*13+t) completion flags
static __device__ int   g_ctr;            // persistent work counter

static __device__ const int g_ToutA[8] = {12,10,9,7,6,4,3,1};
static __device__ const int g_dilA[8]  = {1,2,1,2,1,2,1,2};

// ---- MUFU helpers (SFU pipe; rel err ~1e-6) ---------------------------------
__device__ __forceinline__ float ex2_(float x){ float r; asm("ex2.approx.f32 %0,%1;":"=f"(r):"f"(x)); return r; }
__device__ __forceinline__ float lg2_(float x){ float r; asm("lg2.approx.f32 %0,%1;":"=f"(r):"f"(x)); return r; }
__device__ __forceinline__ float rcp_(float x){ float r; asm("rcp.approx.f32 %0,%1;":"=f"(r):"f"(x)); return r; }

// ---- packed f32x2 helpers (sm_100+) -----------------------------------------
__device__ __forceinline__ ull pack2(float lo, float hi){
  ull r; asm("mov.b64 %0, {%1,%2};" : "=l"(r) : "f"(lo), "f"(hi)); return r;
}
__device__ __forceinline__ void unpack2(ull v, float& lo, float& hi){
  asm("mov.b64 {%0,%1}, %2;" : "=f"(lo), "=f"(hi) : "l"(v));
}
__device__ __forceinline__ ull fma2(ull a, ull b, ull c){
  ull d; asm("fma.rn.f32x2 %0, %1, %2, %3;" : "=l"(d) : "l"(a), "l"(b), "l"(c)); return d;
}
__device__ __forceinline__ ull mul2(ull a, ull b){
  ull d; asm("mul.rn.f32x2 %0, %1, %2;" : "=l"(d) : "l"(a), "l"(b)); return d;
}
__device__ __forceinline__ ull add2(ull a, ull b){
  ull d; asm("add.rn.f32x2 %0, %1, %2;" : "=l"(d) : "l"(a), "l"(b)); return d;
}

__device__ __forceinline__ float dotqk(const ull* qq, const float* kp_f){
  const ulonglong2* kp = (const ulonglong2*)kp_f;
  ulonglong2 kA=kp[0], kB=kp[1], kC=kp[2], kD=kp[3];
  ull d0 = mul2(qq[0],kA.x); d0=fma2(qq[1],kA.y,d0); d0=fma2(qq[2],kB.x,d0); d0=fma2(qq[3],kB.y,d0);
  ull d1 = mul2(qq[4],kC.x); d1=fma2(qq[5],kC.y,d1); d1=fma2(qq[6],kD.x,d1); d1=fma2(qq[7],kD.y,d1);
  float s0,s1,s2,s3; unpack2(d0,s0,s1); unpack2(d1,s2,s3);
  return (s0+s1)+(s2+s3);
}

// ---- start conv + skip zero + flag/counter reset -----------------------------
__global__ __launch_bounds__(256) void start_kernel(const float* __restrict__ x,
                                                    const float* __restrict__ sW,
                                                    const float* __restrict__ sb){
  int i = blockIdx.x*256 + threadIdx.x;
  const int tot = 64*13*CNN;              // 8,652,800
  const int tot2 = tot + 64*256*NN;       // +5,324,800
  if (i < tot){
    int n = i % NN; int r = i / NN;
    int c = r & 31; r >>= 5;
    int t = r % 13; int b = r / 13;
    float v0 = x[((b*2+0)*NN + n)*13 + t];
    float v1 = x[((b*2+1)*NN + n)*13 + t];
    g_X0[i] = fmaf(sW[c*2], v0, fmaf(sW[c*2+1], v1, sb[c]));
  } else if (i < tot2){
    g_skip[i - tot] = 0.f;
  } else {
    int j = i - tot2;
    if (j < 8*832) g_flag[j] = 0;
    else if (j == 8*832) g_ctr = 0;
  }
}

// ---- persistent fused network kernel -----------------------------------------
#define OFF_K     7040
#define OFF_MXP   14080
#define OFF_ZP    14784
#define OFF_GX    15488    // [352][36]
#define OFF_W     28160    // staged weights (max 4192)
#define OFF_ROW   32352    // [352]
#define OFF_WORK  32704
#define LAYER_SMEM_BYTES (32708*4)
#define NTILES 3328

__global__ __launch_bounds__(NT,1) void net_kernel(
    const float* __restrict__ fW,  const float* __restrict__ fb,
    const float* __restrict__ gW,  const float* __restrict__ gb,
    const float* __restrict__ skW, const float* __restrict__ skb,
    const float* __restrict__ qW,  const float* __restrict__ qb,
    const float* __restrict__ kW,  const float* __restrict__ kb,
    const float* __restrict__ mW,  const float* __restrict__ mb,
    const float* __restrict__ bng, const float* __restrict__ bnb,
    const float* __restrict__ bnm, const float* __restrict__ bnv,
    const float* __restrict__ emb)
{
  extern __shared__ __align__(16) float sm[];
  const int tid = threadIdx.x;
  const int n = tid % 352;
  const int h = tid / 352;
  const size_t tile = (size_t)blockIdx.x;   // exclusive scratch slot (persistent)

  float* s_swt = sm;               // [32][256]
  float* s_q   = sm;               // [352][20]
  float* s_k   = sm + OFF_K;       // [352][20]
  float* s_mxp = sm + OFF_MXP;     // [2][352]
  float* s_zp  = sm + OFF_ZP;      // [2][352]
  float* s_xa  = sm;               // [352][36]
  float* s_gx  = sm + OFF_GX;      // [352][36]
  float* wreg  = sm + OFF_W;
  float* s_row = sm + OFF_ROW;
  int*   s_work = (int*)(sm + OFF_WORK);

  for (;;){
    if (tid == 0) *s_work = atomicAdd(&g_ctr, 1);
    __syncthreads();
    const int idx = *s_work;
    if (idx >= NTILES) break;

    // decode layer (prefix: 0,768,1408,1984,2432,2816,3072,3264,3328)
    int layer, base;
    if      (idx <  768){ layer=0; base=0;    }
    else if (idx < 1408){ layer=1; base=768;  }
    else if (idx < 1984){ layer=2; base=1408; }
    else if (idx < 2432){ layer=3; base=1984; }
    else if (idx < 2816){ layer=4; base=2432; }
    else if (idx < 3072){ layer=5; base=2816; }
    else if (idx < 3264){ layer=6; base=3072; }
    else                { layer=7; base=3264; }
    const int r0 = idx - base;
    const int Tout = g_ToutA[layer];
    const int dil  = g_dilA[layer];
    const int t = r0 % Tout, b = r0 / Tout;
    const int do_att = (layer != 7);
    const int last_t = (t == Tout-1);
    const int parity = layer & 1;
    const float* __restrict__ Xin  = parity ? g_X1 : g_X0;
    float* __restrict__       Xout = parity ? g_X0 : g_X1;

    // ---- phase 0: stage gated weights + biases (+ skipW) ----------------------
    for (int idx2 = tid; idx2 < 4096; idx2 += NT){
      int ci = idx2>>7, rr = idx2&127, kind = rr>>5, co = rr&31;
      const float* src = (kind < 2) ? fW : gW;
      wreg[idx2] = src[((layer*32+co)*32+ci)*2 + (kind & 1)];
    }
    if (tid < 64) wreg[4096+tid] = (tid<32) ? fb[layer*32+tid] : gb[layer*32+tid-32];
    if (last_t){
      for (int idx2 = tid; idx2 < 8192; idx2 += NT){
        int ci = idx2>>8, o = idx2&255;
        s_swt[idx2] = skW[(layer*256+o)*32 + ci];
      }
    }
    __syncthreads();

    // ---- dependency wait (overlapped after staging) ---------------------------
    if (layer > 0){
      if (tid == 0){
        volatile int* fl = (volatile int*)(g_flag + (layer-1)*832 + b*13);
        while (fl[t] == 0) __nanosleep(32);
        int t2 = t + dil;
        while (fl[t2] == 0) __nanosleep(32);
        int t3 = t - g_dilA[layer-1];
        if (t3 >= 0) while (fl[t3] == 0) __nanosleep(32);
      }
      __syncthreads();
      __threadfence();
    }

    // ---- phase 1: gated conv (packed f32x2) -----------------------------------
    const int base_in = (b*13 + t)*CNN;
    if (n < NN){
      const float* xin = Xin + base_in + n;
      const float* xrn = xin + dil*CNN;
      ull f2[8], g2[8];
      {
        const ulonglong2* fbp = (const ulonglong2*)(wreg + 4096 + 16*h);
        const ulonglong2* gbp = (const ulonglong2*)(wreg + 4128 + 16*h);
        #pragma unroll
        for (int p=0;p<4;p++){ ulonglong2 a=fbp[p], c=gbp[p]; f2[2*p]=a.x; f2[2*p+1]=a.y; g2[2*p]=c.x; g2[2*p+1]=c.y; }
      }
      #pragma unroll 4
      for (int ci=0; ci<32; ci++){
        float xl = xin[ci*NN], xr = xrn[ci*NN];
        ull xl2 = pack2(xl,xl), xr2 = pack2(xr,xr);
        const ulonglong2* p0 = (const ulonglong2*)(wreg + ci*128      + 16*h);
        const ulonglong2* p1 = (const ulonglong2*)(wreg + ci*128 + 32 + 16*h);
        const ulonglong2* p2 = (const ulonglong2*)(wreg + ci*128 + 64 + 16*h);
        const ulonglong2* p3 = (const ulonglong2*)(wreg + ci*128 + 96 + 16*h);
        #pragma unroll
        for (int p4=0;p4<4;p4++){
          ulonglong2 a=p0[p4], bb=p1[p4], c=p2[p4], d=p3[p4];
          f2[2*p4]   = fma2(xl2, a.x,  f2[2*p4]);   f2[2*p4+1] = fma2(xl2, a.y,  f2[2*p4+1]);
          f2[2*p4]   = fma2(xr2, bb.x, f2[2*p4]);   f2[2*p4+1] = fma2(xr2, bb.y, f2[2*p4+1]);
          g2[2*p4]   = fma2(xl2, c.x,  g2[2*p4]);   g2[2*p4+1] = fma2(xl2, c.y,  g2[2*p4+1]);
          g2[2*p4]   = fma2(xr2, d.x,  g2[2*p4]);   g2[2*p4+1] = fma2(xr2, d.y,  g2[2*p4+1]);
        }
      }
      #pragma unroll
      for (int p=0;p<8;p++){
        float fa,fb2, ga,gb2;
        unpack2(f2[p], fa, fb2); unpack2(g2[p], ga, gb2);
        float efa = ex2_(-2.88539008f*fa), ega = ex2_(-1.44269504f*ga);
        float efb = ex2_(-2.88539008f*fb2), egb = ex2_(-1.44269504f*gb2);
        s_gx[n*36 + 16*h + 2*p]   = (1.f - efa) * rcp_((1.f + efa)*(1.f + ega));
        s_gx[n*36 + 16*h + 2*p+1] = (1.f - efb) * rcp_((1.f + efb)*(1.f + egb));
      }
    }
    __syncthreads();

    // ---- stage attention-phase weights ----------------------------------------
    if (do_att){
      for (int idx2 = tid; idx2 < 1536; idx2 += NT){
        int half = (idx2 >= 768) ? 1 : 0;
        int rr = idx2 - half*768; int cin = rr>>4, d = rr&15;
        wreg[idx2] = (half ? kW : qW)[(layer*16+d)*48 + cin];
      }
      if (tid < 32) wreg[1536+tid] = (tid<16) ? qb[layer*16+tid] : kb[layer*16+tid-16];
      for (int idx2 = tid; idx2 < 2048; idx2 += NT){
        int c = idx2>>5, o = idx2&31;
        wreg[1568+idx2] = mW[(layer*32+o)*64 + c];
      }
      if (tid < 32){
        wreg[3616+tid] = mb[layer*32+tid];
        float sc = bng[layer*32+tid] * rsqrtf(bnv[layer*32+tid] + 1e-5f);
        wreg[3648+tid] = sc;
        wreg[3680+tid] = bnb[layer*32+tid] - bnm[layer*32+tid]*sc;
      }
    }

    // ---- phase 1b: skip contribution (only last time index) -------------------
    if (last_t && n < NN){
      float* skp = g_skip + b*256*NN + n;
      const float4* gxv = (const float4*)(s_gx + n*36);
      #pragma unroll 1
      for (int og=0; og<4; og++){
        int ot = 4*h + og;
        float acc[32];
        #pragma unroll
        for (int j=0;j<32;j++) acc[j] = skb[layer*256 + ot*32 + j];
        #pragma unroll 2
        for (int ci4=0; ci4<8; ci4++){
          float4 g4 = gxv[ci4];
          #pragma unroll
          for (int jj=0; jj<4; jj++){
            float xv = (jj==0)?g4.x:(jj==1)?g4.y:(jj==2)?g4.z:g4.w;
            const float4* wv = (const float4*)(s_swt + (ci4*4+jj)*256 + ot*32);
            #pragma unroll
            for (int j4=0;j4<8;j4++){
              float4 w = wv[j4];
              acc[4*j4+0]=fmaf(w.x,xv,acc[4*j4+0]); acc[4*j4+1]=fmaf(w.y,xv,acc[4*j4+1]);
              acc[4*j4+2]=fmaf(w.z,xv,acc[4*j4+2]); acc[4*j4+3]=fmaf(w.w,xv,acc[4*j4+3]);
            }
          }
        }
        #pragma unroll
        for (int j=0;j<32;j++) skp[(ot*32+j)*NN] += acc[j];
      }
    }

    if (do_att){
      __syncthreads();

      // ---- phase 2: h=0 -> q (log2e/4 folded), h=1 -> k ------------------------
      if (n < NN){
        ull a2[8];
        const float* wb = wreg + 768*h;
        {
          const ulonglong2* bp2 = (const ulonglong2*)(wreg + 1536 + 16*h);
          #pragma unroll
          for (int p=0;p<4;p++){ ulonglong2 v=bp2[p]; a2[2*p]=v.x; a2[2*p+1]=v.y; }
        }
        const float4* gxv = (const float4*)(s_gx + n*36);
        #pragma unroll 2
        for (int ci4=0; ci4<8; ci4++){
          float4 g4 = gxv[ci4];
          #pragma unroll
          for (int jj=0; jj<4; jj++){
            float xv = (jj==0)?g4.x:(jj==1)?g4.y:(jj==2)?g4.z:g4.w;
            ull xv2 = pack2(xv,xv);
            const ulonglong2* wv = (const ulonglong2*)(wb + (ci4*4+jj)*16);
            ulonglong2 wA=wv[0], wB=wv[1], wC=wv[2], wD=wv[3];
            a2[0]=fma2(xv2,wA.x,a2[0]); a2[1]=fma2(xv2,wA.y,a2[1]);
            a2[2]=fma2(xv2,wB.x,a2[2]); a2[3]=fma2(xv2,wB.y,a2[3]);
            a2[4]=fma2(xv2,wC.x,a2[4]); a2[5]=fma2(xv2,wC.y,a2[5]);
            a2[6]=fma2(xv2,wD.x,a2[6]); a2[7]=fma2(xv2,wD.y,a2[7]);
          }
        }
        #pragma unroll 4
        for (int e=0; e<16; e++){
          float xv = emb[e*NN+n];
          ull xv2 = pack2(xv,xv);
          const ulonglong2* wv = (const ulonglong2*)(wb + (32+e)*16);
          ulonglong2 wA=wv[0], wB=wv[1], wC=wv[2], wD=wv[3];
          a2[0]=fma2(xv2,wA.x,a2[0]); a2[1]=fma2(xv2,wA.y,a2[1]);
          a2[2]=fma2(xv2,wB.x,a2[2]); a2[3]=fma2(xv2,wB.y,a2[3]);
          a2[4]=fma2(xv2,wC.x,a2[4]); a2[5]=fma2(xv2,wC.y,a2[5]);
          a2[6]=fma2(xv2,wD.x,a2[6]); a2[7]=fma2(xv2,wD.y,a2[7]);
        }
        if (h == 0){
          ull qsc2 = pack2(0.36067376f, 0.36067376f);
          ull* qp = (ull*)(s_q + n*20);
          #pragma unroll
          for (int p=0;p<8;p++) qp[p] = mul2(a2[p], qsc2);
        } else {
          ull* kp = (ull*)(s_k + n*20);
          #pragma unroll
          for (int p=0;p<8;p++) kp[p] = a2[p];
        }
      }
      __syncthreads();

      // ---- phase 3: scores ONCE -> g_sc; 2-acc online LSE ----------------------
      if (n < NN){
        ull qq[8];
        {
          const ulonglong2* qp = (const ulonglong2*)(s_q + n*20);
          #pragma unroll
          for (int p=0;p<4;p++){ ulonglong2 v=qp[p]; qq[2*p]=v.x; qq[2*p+1]=v.y; }
        }
        float* srow = g_sc + tile*SCT + (size_t)n*328;
        const int c0 = h ? 164 : 0;
        const int nvec = h ? 40 : 41;
        float mxE = -1e30f, ZE = 0.f, mxO = -1e30f, ZO = 0.f;
        #pragma unroll 1
        for (int v=0; v<nvec; v++){
          int c = c0 + 4*v;
          float s0 = dotqk(qq, s_k + (c+0)*20);
          float s1 = dotqk(qq, s_k + (c+1)*20);
          float s2 = dotqk(qq, s_k + (c+2)*20);
          float s3 = dotqk(qq, s_k + (c+3)*20);
          *(float4*)(srow + c) = make_float4(s0,s1,s2,s3);
          float nm;
          nm = fmaxf(mxE, s0); ZE = fmaf(ZE, ex2_(mxE-nm), ex2_(s0-nm)); mxE = nm;
          nm = fmaxf(mxO, s1); ZO = fmaf(ZO, ex2_(mxO-nm), ex2_(s1-nm)); mxO = nm;
          nm = fmaxf(mxE, s2); ZE = fmaf(ZE, ex2_(mxE-nm), ex2_(s2-nm)); mxE = nm;
          nm = fmaxf(mxO, s3); ZO = fmaf(ZO, ex2_(mxO-nm), ex2_(s3-nm)); mxO = nm;
        }
        if (h){
          float s0 = dotqk(qq, s_k + 324*20);
          srow[324] = s0;
          float nm = fmaxf(mxE, s0); ZE = fmaf(ZE, ex2_(mxE-nm), ex2_(s0-nm)); mxE = nm;
        }
        float mx = fmaxf(mxE, mxO);
        float Z  = ZE*ex2_(mxE-mx) + ZO*ex2_(mxO-mx);
        s_mxp[h*352+n] = mx;
        s_zp [h*352+n] = Z;
      }
      __syncthreads();
      if (h == 0 && n < NN){
        float mx0 = s_mxp[n], mx1 = s_mxp[352+n];
        float mx  = fmaxf(mx0, mx1);
        float Z   = s_zp[n]*ex2_(mx0-mx) + s_zp[352+n]*ex2_(mx1-mx);
        s_row[n]  = mx + lg2_(Z);
      }
      __syncthreads();

      // ---- phase 4: weighted sum from stored scores ----------------------------
      const int warp = tid >> 5, lane = tid & 31;
      const int bmh = warp & 1;
      const int bp  = (warp >> 1)*16 + (lane >> 1);
      const int bch = lane & 1;
      const int j1  = 2*bp, j2 = 2*bp + 1;

      ull xaA[8], xaB[8];
      #pragma unroll
      for (int p=0;p<8;p++){ xaA[p]=0ULL; xaB[p]=0ULL; }
      {
        const int mbase  = bmh ? 163 : 0;
        const int mcount = bmh ? 162 : 163;
        const float* sp2 = g_sc + tile*SCT + (size_t)mbase*328 + j1;
        #pragma unroll 8
        for (int i=0; i<mcount; i++){
          int m = mbase + i;
          float2 sc = *(const float2*)(sp2 + (size_t)i*328);
          float rw = s_row[m];
          float w1 = ex2_(sc.x - rw), w2 = ex2_(sc.y - rw);
          ull w12 = pack2(w1,w1), w22 = pack2(w2,w2);
          const ulonglong2* gv = (const ulonglong2*)(s_gx + m*36 + 16*bch);
          ulonglong2 gA=gv[0], gB=gv[1], gC=gv[2], gD=gv[3];
          xaA[0]=fma2(w12,gA.x,xaA[0]); xaA[1]=fma2(w12,gA.y,xaA[1]);
          xaA[2]=fma2(w12,gB.x,xaA[2]); xaA[3]=fma2(w12,gB.y,xaA[3]);
          xaA[4]=fma2(w12,gC.x,xaA[4]); xaA[5]=fma2(w12,gC.y,xaA[5]);
          xaA[6]=fma2(w12,gD.x,xaA[6]); xaA[7]=fma2(w12,gD.y,xaA[7]);
          xaB[0]=fma2(w22,gA.x,xaB[0]); xaB[1]=fma2(w22,gA.y,xaB[1]);
          xaB[2]=fma2(w22,gB.x,xaB[2]); xaB[3]=fma2(w22,gB.y,xaB[3]);
          xaB[4]=fma2(w22,gC.x,xaB[4]); xaB[5]=fma2(w22,gC.y,xaB[5]);
          xaB[6]=fma2(w22,gD.x,xaB[6]); xaB[7]=fma2(w22,gD.y,xaB[7]);
        }
      }
      __syncthreads();
      if (bmh == 0 && j1 < NN){
        ulonglong2* xp1 = (ulonglong2*)(s_xa + j1*36 + 16*bch);
        xp1[0]=make_ulonglong2(xaA[0],xaA[1]); xp1[1]=make_ulonglong2(xaA[2],xaA[3]);
        xp1[2]=make_ulonglong2(xaA[4],xaA[5]); xp1[3]=make_ulonglong2(xaA[6],xaA[7]);
        if (j2 < NN){
          ulonglong2* xp2 = (ulonglong2*)(s_xa + j2*36 + 16*bch);
          xp2[0]=make_ulonglong2(xaB[0],xaB[1]); xp2[1]=make_ulonglong2(xaB[2],xaB[3]);
          xp2[2]=make_ulonglong2(xaB[4],xaB[5]); xp2[3]=make_ulonglong2(xaB[6],xaB[7]);
        }
      }
      __syncthreads();
      if (bmh == 1 && j1 < NN){
        ull* xp1 = (ull*)(s_xa + j1*36 + 16*bch);
        #pragma unroll
        for (int p=0;p<8;p++) xp1[p] = add2(xp1[p], xaA[p]);
        if (j2 < NN){
          ull* xp2 = (ull*)(s_xa + j2*36 + 16*bch);
          #pragma unroll
          for (int p=0;p<8;p++) xp2[p] = add2(xp2[p], xaB[p]);
        }
      }
      __syncthreads();

      // ---- phase 5: mlp (packed) + residual + BN -------------------------------
      if (n < NN){
        ull o2[8];
        {
          const ulonglong2* bp2 = (const ulonglong2*)(wreg + 3616 + 16*h);
          #pragma unroll
          for (int p=0;p<4;p++){ ulonglong2 v=bp2[p]; o2[2*p]=v.x; o2[2*p+1]=v.y; }
        }
        const float4* gxv = (const float4*)(s_gx + n*36);
        const float4* xav = (const float4*)(s_xa + n*36);
        #pragma unroll 2
        for (int ci4=0; ci4<8; ci4++){
          float4 g4 = gxv[ci4];
          #pragma unroll
          for (int jj=0; jj<4; jj++){
            float xv = (jj==0)?g4.x:(jj==1)?g4.y:(jj==2)?g4.z:g4.w;
            ull xv2 = pack2(xv,xv);
            const ulonglong2* wv = (const ulonglong2*)(wreg + 1568 + (ci4*4+jj)*32 + 16*h);
            ulonglong2 wA=wv[0], wB=wv[1];
            o2[0]=fma2(xv2,wA.x,o2[0]); o2[1]=fma2(xv2,wA.y,o2[1]);
            o2[2]=fma2(xv2,wB.x,o2[2]); o2[3]=fma2(xv2,wB.y,o2[3]);
            wA=wv[2]; wB=wv[3];
            o2[4]=fma2(xv2,wA.x,o2[4]); o2[5]=fma2(xv2,wA.y,o2[5]);
            o2[6]=fma2(xv2,wB.x,o2[6]); o2[7]=fma2(xv2,wB.y,o2[7]);
          }
        }
        #pragma unroll 2
        for (int ci4=0; ci4<8; ci4++){
          float4 g4 = xav[ci4];
          #pragma unroll
          for (int jj=0; jj<4; jj++){
            float xv = (jj==0)?g4.x:(jj==1)?g4.y:(jj==2)?g4.z:g4.w;
            ull xv2 = pack2(xv,xv);
            const ulonglong2* wv = (const ulonglong2*)(wreg + 1568 + (32+ci4*4+jj)*32 + 16*h);
            ulonglong2 wA=wv[0], wB=wv[1];
            o2[0]=fma2(xv2,wA.x,o2[0]); o2[1]=fma2(xv2,wA.y,o2[1]);
            o2[2]=fma2(xv2,wB.x,o2[2]); o2[3]=fma2(xv2,wB.y,o2[3]);
            wA=wv[2]; wB=wv[3];
            o2[4]=fma2(xv2,wA.x,o2[4]); o2[5]=fma2(xv2,wA.y,o2[5]);
            o2[6]=fma2(xv2,wB.x,o2[6]); o2[7]=fma2(xv2,wB.y,o2[7]);
          }
        }
        const float* rin = Xin + base_in + dil*CNN + n;
        float* outp = Xout + base_in + n;
        #pragma unroll
        for (int p=0; p<8; p++){
          float va, vb; unpack2(o2[p], va, vb);
          int c0 = 16*h + 2*p, c1 = c0 + 1;
          float v0 = va + rin[c0*NN];
          float v1 = vb + rin[c1*NN];
          outp[c0*NN] = fmaf(v0, wreg[3648+c0], wreg[3680+c0]);
          outp[c1*NN] = fmaf(v1, wreg[3648+c1], wreg[3680+c1]);
        }
      }
    }

    // ---- publish tile completion ----------------------------------------------
    __threadfence();
    __syncthreads();
    if (tid == 0) atomicExch(&g_flag[layer*832 + b*13 + t], 1);
  }
}

// ---- head: relu(skip) -> relu(512) -> 12 ------------------------------------
#define H_SS 0
#define H_W1 16384
#define H_H  32832
#define H_W2 37184
#define H_B1 43328
#define HEAD_SMEM_BYTES (43840*4)

__global__ __launch_bounds__(256,1) void head_kernel(
    const float* __restrict__ w1, const float* __restrict__ b1,
    const float* __restrict__ w2, const float* __restrict__ b2,
    float* __restrict__ out)
{
  extern __shared__ __align__(16) float sm[];
  float* s_s = sm + H_SS;   // [256][64]
  float* w1s = sm + H_W1;   // [64][257]
  float* h_s = sm + H_H;    // [64][68]
  float* w2t = sm + H_W2;   // [512][12]
  float* b1s = sm + H_B1;   // [512]
  const int tid = threadIdx.x;
  const int p0 = blockIdx.x*64;

  for (int idx = tid; idx < 16384; idx += 256){
    int c = idx>>6, j = idx&63, p = p0 + j;
    int b = p/NN, nn = p - b*NN;
    s_s[idx] = fmaxf(g_skip[(b*256+c)*NN + nn], 0.f);
  }
  for (int idx = tid; idx < 6144; idx += 256){
    int o = idx/12, oo = idx - o*12;
    w2t[idx] = w2[oo*512 + o];
  }
  for (int idx = tid; idx < 512; idx += 256) b1s[idx] = b1[idx];

  const int op  = tid & 63, jg = tid >> 6;
  const int oo  = tid % 12, j0 = (tid/12)*4;
  float accO[4] = {0.f,0.f,0.f,0.f};

  for (int ot = 0; ot < 8; ot++){
    __syncthreads();
    for (int idx = tid; idx < 16384; idx += 256){
      int o = idx>>8, c = idx&255;
      w1s[o*257+c] = w1[(ot*64+o)*256 + c];
    }
    __syncthreads();
    {
      float acc[16];
      float bv = b1s[ot*64+op];
      #pragma unroll
      for (int k=0;k<16;k++) acc[k]=bv;
      #pragma unroll 2
      for (int c=0; c<256; c++){
        float w = w1s[op*257+c];
        const float4* sp = (const float4*)(s_s + c*64 + jg*16);
        #pragma unroll
        for (int k4=0;k4<4;k4++){
          float4 s4 = sp[k4];
          acc[4*k4+0]=fmaf(w,s4.x,acc[4*k4+0]); acc[4*k4+1]=fmaf(w,s4.y,acc[4*k4+1]);
          acc[4*k4+2]=fmaf(w,s4.z,acc[4*k4+2]); acc[4*k4+3]=fmaf(w,s4.w,acc[4*k4+3]);
        }
      }
      float4* hp = (float4*)(h_s + op*68 + jg*16);
      #pragma unroll
      for (int k4=0;k4<4;k4++)
        hp[k4] = make_float4(fmaxf(acc[4*k4+0],0.f), fmaxf(acc[4*k4+1],0.f),
                             fmaxf(acc[4*k4+2],0.f), fmaxf(acc[4*k4+3],0.f));
    }
    __syncthreads();
    if (tid < 192){
      #pragma unroll 4
      for (int o=0; o<64; o++){
        float w = w2t[(ot*64+o)*12 + oo];
        const float4* hp = (const float4*)(h_s + o*68 + j0);
        float4 h4 = hp[0];
        accO[0]=fmaf(w,h4.x,accO[0]); accO[1]=fmaf(w,h4.y,accO[1]);
        accO[2]=fmaf(w,h4.z,accO[2]); accO[3]=fmaf(w,h4.w,accO[3]);
      }
    }
  }
  if (tid < 192){
    float bb = b2[oo];
    #pragma unroll
    for (int k=0;k<4;k++){
      int p = p0 + j0 + k;
      int b = p/NN, nn = p - b*NN;
      out[(b*12+oo)*NN + nn] = accO[k] + bb;
    }
  }
}

// ---- host -------------------------------------------------------------------
extern "C" void kernel_launch(void* const* d_in, const int* in_sizes, int n_in,
                              void* d_out, int out_size){
  const float* x    = (const float*)d_in[0];
  const float* emb  = (const float*)d_in[1];
  const float* stW  = (const float*)d_in[2];
  const float* stb  = (const float*)d_in[3];
  const float* fW   = (const float*)d_in[4];
  const float* fb   = (const float*)d_in[5];
  const float* gW   = (const float*)d_in[6];
  const float* gb   = (const float*)d_in[7];
  const float* skW  = (const float*)d_in[8];
  const float* skb  = (const float*)d_in[9];
  const float* qW   = (const float*)d_in[10];
  const float* qb   = (const float*)d_in[11];
  const float* kW   = (const float*)d_in[12];
  const float* kb   = (const float*)d_in[13];
  const float* mW   = (const float*)d_in[14];
  const float* mb   = (const float*)d_in[15];
  const float* bng  = (const float*)d_in[16];
  const float* bnb  = (const float*)d_in[17];
  const float* bnm  = (const float*)d_in[18];
  const float* bnv  = (const float*)d_in[19];
  const float* e1W  = (const float*)d_in[20];
  const float* e1b  = (const float*)d_in[21];
  const float* e2W  = (const float*)d_in[22];
  const float* e2b  = (const float*)d_in[23];
  float* out = (float*)d_out;

  cudaFuncSetAttribute(net_kernel,  cudaFuncAttributeMaxDynamicSharedMemorySize, LAYER_SMEM_BYTES);
  cudaFuncSetAttribute(head_kernel, cudaFuncAttributeMaxDynamicSharedMemorySize, HEAD_SMEM_BYTES);

  start_kernel<<<54627, 256>>>(x, stW, stb);

  net_kernel<<<148, NT, LAYER_SMEM_BYTES>>>(
      fW, fb, gW, gb, skW, skb, qW, qb, kW, kb, mW, mb,
      bng, bnb, bnm, bnv, emb);

  head_kernel<<<325, 256, HEAD_SMEM_BYTES>>>(e1W, e1b, e2W, e2b, out);
}

// round 17
// speedup vs baseline: 1.2787x; 1.0048x over previous
#include <cuda_runtime.h>

#define NN 325
#define CNN (32*NN)
#define NT 704          // 2 threads per node slot for phases 1/2/5

typedef unsigned long long ull;

static __device__ float g_X0[64*13*CNN];
static __device__ float g_X1[64*13*CNN];
static __device__ float g_skip[64*256*NN];
#define SCT (328*328)
static __device__ float g_sc[256u*SCT];   // per-block score scratch, L2-resident
static __device__ int   g_flag[8*832];    // per (layer, b*13+t) completion flags
static __device__ int   g_ctr;            // persistent work counter

static __device__ const int g_ToutA[8] = {12,10,9,7,6,4,3,1};
static __device__ const int g_dilA[8]  = {1,2,1,2,1,2,1,2};

// ---- MUFU helpers (SFU pipe; rel err ~1e-6) ---------------------------------
__device__ __forceinline__ float ex2_(float x){ float r; asm("ex2.approx.f32 %0,%1;":"=f"(r):"f"(x)); return r; }
__device__ __forceinline__ float lg2_(float x){ float r; asm("lg2.approx.f32 %0,%1;":"=f"(r):"f"(x)); return r; }
__device__ __forceinline__ float rcp_(float x){ float r; asm("rcp.approx.f32 %0,%1;":"=f"(r):"f"(x)); return r; }

// ---- packed f32x2 helpers (sm_100+) -----------------------------------------
__device__ __forceinline__ ull pack2(float lo, float hi){
  ull r; asm("mov.b64 %0, {%1,%2};" : "=l"(r) : "f"(lo), "f"(hi)); return r;
}
__device__ __forceinline__ void unpack2(ull v, float& lo, float& hi){
  asm("mov.b64 {%0,%1}, %2;" : "=f"(lo), "=f"(hi) : "l"(v));
}
__device__ __forceinline__ ull fma2(ull a, ull b, ull c){
  ull d; asm("fma.rn.f32x2 %0, %1, %2, %3;" : "=l"(d) : "l"(a), "l"(b), "l"(c)); return d;
}
__device__ __forceinline__ ull mul2(ull a, ull b){
  ull d; asm("mul.rn.f32x2 %0, %1, %2;" : "=l"(d) : "l"(a), "l"(b)); return d;
}
__device__ __forceinline__ ull add2(ull a, ull b){
  ull d; asm("add.rn.f32x2 %0, %1, %2;" : "=l"(d) : "l"(a), "l"(b)); return d;
}

__device__ __forceinline__ float dotqk(const ull* qq, const float* kp_f){
  const ulonglong2* kp = (const ulonglong2*)kp_f;
  ulonglong2 kA=kp[0], kB=kp[1], kC=kp[2], kD=kp[3];
  ull d0 = mul2(qq[0],kA.x); d0=fma2(qq[1],kA.y,d0); d0=fma2(qq[2],kB.x,d0); d0=fma2(qq[3],kB.y,d0);
  ull d1 = mul2(qq[4],kC.x); d1=fma2(qq[5],kC.y,d1); d1=fma2(qq[6],kD.x,d1); d1=fma2(qq[7],kD.y,d1);
  float s0,s1,s2,s3; unpack2(d0,s0,s1); unpack2(d1,s2,s3);
  return (s0+s1)+(s2+s3);
}

// ---- start conv + skip zero + flag/counter reset -----------------------------
__global__ __launch_bounds__(256) void start_kernel(const float* __restrict__ x,
                                                    const float* __restrict__ sW,
                                                    const float* __restrict__ sb){
  int i = blockIdx.x*256 + threadIdx.x;
  const int tot = 64*13*CNN;              // 8,652,800
  const int tot2 = tot + 64*256*NN;       // +5,324,800
  if (i < tot){
    int n = i % NN; int r = i / NN;
    int c = r & 31; r >>= 5;
    int t = r % 13; int b = r / 13;
    float v0 = x[((b*2+0)*NN + n)*13 + t];
    float v1 = x[((b*2+1)*NN + n)*13 + t];
    g_X0[i] = fmaf(sW[c*2], v0, fmaf(sW[c*2+1], v1, sb[c]));
  } else if (i < tot2){
    g_skip[i - tot] = 0.f;
  } else {
    int j = i - tot2;
    if (j < 8*832) g_flag[j] = 0;
    else if (j == 8*832) g_ctr = 0;
  }
}

// ---- persistent fused network + head kernel ----------------------------------
#define OFF_K     7040
#define OFF_MXP   14080
#define OFF_ZP    14784
#define OFF_GX    15488    // [352][36]
#define OFF_W     28160    // staged weights (max 4192)
#define OFF_ROW   32352    // [352]
// head overlay: s_s[256][48]@0, w1[64][257]@12288, h[64][48]@28736,
//               w2t[512][12]@31808, b1[512]@37952  (ends 38464)
#define OFF_HW1   12288
#define OFF_HH    28736
#define OFF_HW2   31808
#define OFF_HB1   37952
#define OFF_WORK  38464
#define LAYER_SMEM_BYTES (38468*4)
#define NTILES_L  3328
#define NHEAD     473          // ceil(20800/44)
#define NTILES_ALL (NTILES_L + NHEAD)

__global__ __launch_bounds__(NT,1) void net_kernel(
    const float* __restrict__ fW,  const float* __restrict__ fb,
    const float* __restrict__ gW,  const float* __restrict__ gb,
    const float* __restrict__ skW, const float* __restrict__ skb,
    const float* __restrict__ qW,  const float* __restrict__ qb,
    const float* __restrict__ kW,  const float* __restrict__ kb,
    const float* __restrict__ mW,  const float* __restrict__ mb,
    const float* __restrict__ bng, const float* __restrict__ bnb,
    const float* __restrict__ bnm, const float* __restrict__ bnv,
    const float* __restrict__ emb,
    const float* __restrict__ e1W, const float* __restrict__ e1b,
    const float* __restrict__ e2W, const float* __restrict__ e2b,
    float* __restrict__ out)
{
  extern __shared__ __align__(16) float sm[];
  const int tid = threadIdx.x;
  const int n = tid % 352;
  const int h = tid / 352;
  const size_t tile = (size_t)blockIdx.x;   // exclusive scratch slot (persistent)

  float* s_swt = sm;               // [32][256]
  float* s_q   = sm;               // [352][20]
  float* s_k   = sm + OFF_K;       // [352][20]
  float* s_mxp = sm + OFF_MXP;     // [2][352]
  float* s_zp  = sm + OFF_ZP;      // [2][352]
  float* s_xa  = sm;               // [352][36]
  float* s_gx  = sm + OFF_GX;      // [352][36]
  float* wreg  = sm + OFF_W;
  float* s_row = sm + OFF_ROW;
  int*   s_work = (int*)(sm + OFF_WORK);

  for (;;){
    if (tid == 0) *s_work = atomicAdd(&g_ctr, 1);
    __syncthreads();
    const int idx = *s_work;
    if (idx >= NTILES_ALL) break;

    // ================= HEAD TILE ==============================================
    if (idx >= NTILES_L){
      const int p0 = (idx - NTILES_L)*44;
      if (tid == 0){
        int p_end = p0 + 43; if (p_end > 20799) p_end = 20799;
        int b_lo = p0/NN, b_hi = p_end/NN;
        volatile int* fl7 = (volatile int*)(g_flag + 7*832);
        while (fl7[b_lo*13] == 0) __nanosleep(32);
        if (b_hi != b_lo) while (fl7[b_hi*13] == 0) __nanosleep(32);
      }
      __syncthreads();
      __threadfence();
      float* hs_s = sm;                // [256][48]
      float* hw1  = sm + OFF_HW1;      // [64][257]
      float* hh   = sm + OFF_HH;       // [64][48]
      float* hw2  = sm + OFF_HW2;      // [512][12]
      float* hb1  = sm + OFF_HB1;      // [512]
      for (int i2 = tid; i2 < 256*44; i2 += NT){
        int c = i2/44, j = i2 - c*44;
        int p = p0 + j;
        float v = 0.f;
        if (p < 20800){
          int bb = p/NN, nn = p - bb*NN;
          v = fmaxf(__ldcg(&g_skip[(bb*256+c)*NN + nn]), 0.f);   // L2-only read
        }
        hs_s[c*48 + j] = v;
      }
      for (int i2 = tid; i2 < 6144; i2 += NT){
        int o = i2/12, oo2 = i2 - o*12;
        hw2[i2] = e2W[oo2*512 + o];
      }
      for (int i2 = tid; i2 < 512; i2 += NT) hb1[i2] = e1b[i2];

      const int fo = tid & 63, fjg = tid >> 6;     // compute role (64 x 11)
      const int foo = tid % 12, fj = tid / 12;     // fold role (tid<528)
      float accO = 0.f;

      #pragma unroll 1
      for (int ot = 0; ot < 8; ot++){
        __syncthreads();                            // prior fold done / staging done
        for (int i2 = tid; i2 < 16384; i2 += NT){
          int o = i2 >> 8, c = i2 & 255;
          hw1[o*257 + c] = e1W[(ot*64 + o)*256 + c];
        }
        __syncthreads();
        {
          float bv = hb1[ot*64 + fo];
          ull a0 = pack2(bv,bv), a1 = pack2(bv,bv);
          const float* wrow = hw1 + fo*257;
          const char* sbase = (const char*)(hs_s + fjg*4);
          #pragma unroll 4
          for (int c = 0; c < 256; c++){
            float w = wrow[c];
            ull w2p = pack2(w,w);
            ulonglong2 s4 = *(const ulonglong2*)(sbase + (size_t)c*192);
            a0 = fma2(w2p, s4.x, a0);
            a1 = fma2(w2p, s4.y, a1);
          }
          float v0,v1,v2,v3; unpack2(a0,v0,v1); unpack2(a1,v2,v3);
          *(float4*)(hh + fo*48 + fjg*4) =
              make_float4(fmaxf(v0,0.f), fmaxf(v1,0.f), fmaxf(v2,0.f), fmaxf(v3,0.f));
        }
        __syncthreads();
        if (tid < 528){
          const float* hcol = hh + fj;
          const float* w2c  = hw2 + ot*64*12 + foo;
          #pragma unroll 8
          for (int o = 0; o < 64; o++)
            accO = fmaf(w2c[o*12], hcol[o*48], accO);
        }
      }
      if (tid < 528){
        int p = p0 + fj;
        if (p < 20800){
          int bb = p/NN, nn = p - bb*NN;
          out[(bb*12 + foo)*NN + nn] = accO + e2b[foo];
        }
      }
      continue;
    }

    // ================= LAYER TILE =============================================
    // decode layer (prefix: 0,768,1408,1984,2432,2816,3072,3264,3328)
    int layer, base;
    if      (idx <  768){ layer=0; base=0;    }
    else if (idx < 1408){ layer=1; base=768;  }
    else if (idx < 1984){ layer=2; base=1408; }
    else if (idx < 2432){ layer=3; base=1984; }
    else if (idx < 2816){ layer=4; base=2432; }
    else if (idx < 3072){ layer=5; base=2816; }
    else if (idx < 3264){ layer=6; base=3072; }
    else                { layer=7; base=3264; }
    const int r0 = idx - base;
    const int Tout = g_ToutA[layer];
    const int dil  = g_dilA[layer];
    const int t = r0 % Tout, b = r0 / Tout;
    const int do_att = (layer != 7);
    const int last_t = (t == Tout-1);
    const int parity = layer & 1;
    const float* __restrict__ Xin  = parity ? g_X1 : g_X0;
    float* __restrict__       Xout = parity ? g_X0 : g_X1;

    // ---- phase 0: stage gated weights + biases (+ skipW) ----------------------
    for (int idx2 = tid; idx2 < 4096; idx2 += NT){
      int ci = idx2>>7, rr = idx2&127, kind = rr>>5, co = rr&31;
      const float* src = (kind < 2) ? fW : gW;
      wreg[idx2] = src[((layer*32+co)*32+ci)*2 + (kind & 1)];
    }
    if (tid < 64) wreg[4096+tid] = (tid<32) ? fb[layer*32+tid] : gb[layer*32+tid-32];
    if (last_t){
      for (int idx2 = tid; idx2 < 8192; idx2 += NT){
        int ci = idx2>>8, o = idx2&255;
        s_swt[idx2] = skW[(layer*256+o)*32 + ci];
      }
    }
    __syncthreads();

    // ---- dependency wait (overlapped after staging) ---------------------------
    if (layer > 0){
      if (tid == 0){
        volatile int* fl = (volatile int*)(g_flag + (layer-1)*832 + b*13);
        while (fl[t] == 0) __nanosleep(32);
        int t2 = t + dil;
        while (fl[t2] == 0) __nanosleep(32);
        int t3 = t - g_dilA[layer-1];
        if (t3 >= 0) while (fl[t3] == 0) __nanosleep(32);
      }
      __syncthreads();
      __threadfence();
    }

    // ---- phase 1: gated conv (packed f32x2) -----------------------------------
    const int base_in = (b*13 + t)*CNN;
    if (n < NN){
      const float* xin = Xin + base_in + n;
      const float* xrn = xin + dil*CNN;
      ull f2[8], g2[8];
      {
        const ulonglong2* fbp = (const ulonglong2*)(wreg + 4096 + 16*h);
        const ulonglong2* gbp = (const ulonglong2*)(wreg + 4128 + 16*h);
        #pragma unroll
        for (int p=0;p<4;p++){ ulonglong2 a=fbp[p], c=gbp[p]; f2[2*p]=a.x; f2[2*p+1]=a.y; g2[2*p]=c.x; g2[2*p+1]=c.y; }
      }
      #pragma unroll 4
      for (int ci=0; ci<32; ci++){
        float xl = xin[ci*NN], xr = xrn[ci*NN];
        ull xl2 = pack2(xl,xl), xr2 = pack2(xr,xr);
        const ulonglong2* p0p = (const ulonglong2*)(wreg + ci*128      + 16*h);
        const ulonglong2* p1p = (const ulonglong2*)(wreg + ci*128 + 32 + 16*h);
        const ulonglong2* p2p = (const ulonglong2*)(wreg + ci*128 + 64 + 16*h);
        const ulonglong2* p3p = (const ulonglong2*)(wreg + ci*128 + 96 + 16*h);
        #pragma unroll
        for (int p4=0;p4<4;p4++){
          ulonglong2 a=p0p[p4], bb=p1p[p4], c=p2p[p4], d=p3p[p4];
          f2[2*p4]   = fma2(xl2, a.x,  f2[2*p4]);   f2[2*p4+1] = fma2(xl2, a.y,  f2[2*p4+1]);
          f2[2*p4]   = fma2(xr2, bb.x, f2[2*p4]);   f2[2*p4+1] = fma2(xr2, bb.y, f2[2*p4+1]);
          g2[2*p4]   = fma2(xl2, c.x,  g2[2*p4]);   g2[2*p4+1] = fma2(xl2, c.y,  g2[2*p4+1]);
          g2[2*p4]   = fma2(xr2, d.x,  g2[2*p4]);   g2[2*p4+1] = fma2(xr2, d.y,  g2[2*p4+1]);
        }
      }
      #pragma unroll
      for (int p=0;p<8;p++){
        float fa,fb2, ga,gb2;
        unpack2(f2[p], fa, fb2); unpack2(g2[p], ga, gb2);
        float efa = ex2_(-2.88539008f*fa), ega = ex2_(-1.44269504f*ga);
        float efb = ex2_(-2.88539008f*fb2), egb = ex2_(-1.44269504f*gb2);
        s_gx[n*36 + 16*h + 2*p]   = (1.f - efa) * rcp_((1.f + efa)*(1.f + ega));
        s_gx[n*36 + 16*h + 2*p+1] = (1.f - efb) * rcp_((1.f + efb)*(1.f + egb));
      }
    }
    __syncthreads();

    // ---- stage attention-phase weights ----------------------------------------
    if (do_att){
      for (int idx2 = tid; idx2 < 1536; idx2 += NT){
        int half = (idx2 >= 768) ? 1 : 0;
        int rr = idx2 - half*768; int cin = rr>>4, d = rr&15;
        wreg[idx2] = (half ? kW : qW)[(layer*16+d)*48 + cin];
      }
      if (tid < 32) wreg[1536+tid] = (tid<16) ? qb[layer*16+tid] : kb[layer*16+tid-16];
      for (int idx2 = tid; idx2 < 2048; idx2 += NT){
        int c = idx2>>5, o = idx2&31;
        wreg[1568+idx2] = mW[(layer*32+o)*64 + c];
      }
      if (tid < 32){
        wreg[3616+tid] = mb[layer*32+tid];
        float sc = bng[layer*32+tid] * rsqrtf(bnv[layer*32+tid] + 1e-5f);
        wreg[3648+tid] = sc;
        wreg[3680+tid] = bnb[layer*32+tid] - bnm[layer*32+tid]*sc;
      }
    }

    // ---- phase 1b: skip contribution (only last time index) -------------------
    if (last_t && n < NN){
      float* skp = g_skip + b*256*NN + n;
      const float4* gxv = (const float4*)(s_gx + n*36);
      #pragma unroll 1
      for (int og=0; og<4; og++){
        int ot = 4*h + og;
        float acc[32];
        #pragma unroll
        for (int j=0;j<32;j++) acc[j] = skb[layer*256 + ot*32 + j];
        #pragma unroll 2
        for (int ci4=0; ci4<8; ci4++){
          float4 g4 = gxv[ci4];
          #pragma unroll
          for (int jj=0; jj<4; jj++){
            float xv = (jj==0)?g4.x:(jj==1)?g4.y:(jj==2)?g4.z:g4.w;
            const float4* wv = (const float4*)(s_swt + (ci4*4+jj)*256 + ot*32);
            #pragma unroll
            for (int j4=0;j4<8;j4++){
              float4 w = wv[j4];
              acc[4*j4+0]=fmaf(w.x,xv,acc[4*j4+0]); acc[4*j4+1]=fmaf(w.y,xv,acc[4*j4+1]);
              acc[4*j4+2]=fmaf(w.z,xv,acc[4*j4+2]); acc[4*j4+3]=fmaf(w.w,xv,acc[4*j4+3]);
            }
          }
        }
        #pragma unroll
        for (int j=0;j<32;j++) skp[(ot*32+j)*NN] += acc[j];
      }
    }

    if (do_att){
      __syncthreads();

      // ---- phase 2: h=0 -> q (log2e/4 folded), h=1 -> k ------------------------
      if (n < NN){
        ull a2[8];
        const float* wb = wreg + 768*h;
        {
          const ulonglong2* bp2 = (const ulonglong2*)(wreg + 1536 + 16*h);
          #pragma unroll
          for (int p=0;p<4;p++){ ulonglong2 v=bp2[p]; a2[2*p]=v.x; a2[2*p+1]=v.y; }
        }
        const float4* gxv = (const float4*)(s_gx + n*36);
        #pragma unroll 2
        for (int ci4=0; ci4<8; ci4++){
          float4 g4 = gxv[ci4];
          #pragma unroll
          for (int jj=0; jj<4; jj++){
            float xv = (jj==0)?g4.x:(jj==1)?g4.y:(jj==2)?g4.z:g4.w;
            ull xv2 = pack2(xv,xv);
            const ulonglong2* wv = (const ulonglong2*)(wb + (ci4*4+jj)*16);
            ulonglong2 wA=wv[0], wB=wv[1], wC=wv[2], wD=wv[3];
            a2[0]=fma2(xv2,wA.x,a2[0]); a2[1]=fma2(xv2,wA.y,a2[1]);
            a2[2]=fma2(xv2,wB.x,a2[2]); a2[3]=fma2(xv2,wB.y,a2[3]);
            a2[4]=fma2(xv2,wC.x,a2[4]); a2[5]=fma2(xv2,wC.y,a2[5]);
            a2[6]=fma2(xv2,wD.x,a2[6]); a2[7]=fma2(xv2,wD.y,a2[7]);
          }
        }
        #pragma unroll 4
        for (int e=0; e<16; e++){
          float xv = emb[e*NN+n];
          ull xv2 = pack2(xv,xv);
          const ulonglong2* wv = (const ulonglong2*)(wb + (32+e)*16);
          ulonglong2 wA=wv[0], wB=wv[1], wC=wv[2], wD=wv[3];
          a2[0]=fma2(xv2,wA.x,a2[0]); a2[1]=fma2(xv2,wA.y,a2[1]);
          a2[2]=fma2(xv2,wB.x,a2[2]); a2[3]=fma2(xv2,wB.y,a2[3]);
          a2[4]=fma2(xv2,wC.x,a2[4]); a2[5]=fma2(xv2,wC.y,a2[5]);
          a2[6]=fma2(xv2,wD.x,a2[6]); a2[7]=fma2(xv2,wD.y,a2[7]);
        }
        if (h == 0){
          ull qsc2 = pack2(0.36067376f, 0.36067376f);
          ull* qp = (ull*)(s_q + n*20);
          #pragma unroll
          for (int p=0;p<8;p++) qp[p] = mul2(a2[p], qsc2);
        } else {
          ull* kp = (ull*)(s_k + n*20);
          #pragma unroll
          for (int p=0;p<8;p++) kp[p] = a2[p];
        }
      }
      __syncthreads();

      // ---- phase 3: scores ONCE -> g_sc; 2-acc online LSE ----------------------
      if (n < NN){
        ull qq[8];
        {
          const ulonglong2* qp = (const ulonglong2*)(s_q + n*20);
          #pragma unroll
          for (int p=0;p<4;p++){ ulonglong2 v=qp[p]; qq[2*p]=v.x; qq[2*p+1]=v.y; }
        }
        float* srow = g_sc + tile*SCT + (size_t)n*328;
        const int c0 = h ? 164 : 0;
        const int nvec = h ? 40 : 41;
        float mxE = -1e30f, ZE = 0.f, mxO = -1e30f, ZO = 0.f;
        #pragma unroll 1
        for (int v=0; v<nvec; v++){
          int c = c0 + 4*v;
          float s0 = dotqk(qq, s_k + (c+0)*20);
          float s1 = dotqk(qq, s_k + (c+1)*20);
          float s2 = dotqk(qq, s_k + (c+2)*20);
          float s3 = dotqk(qq, s_k + (c+3)*20);
          *(float4*)(srow + c) = make_float4(s0,s1,s2,s3);
          float nm;
          nm = fmaxf(mxE, s0); ZE = fmaf(ZE, ex2_(mxE-nm), ex2_(s0-nm)); mxE = nm;
          nm = fmaxf(mxO, s1); ZO = fmaf(ZO, ex2_(mxO-nm), ex2_(s1-nm)); mxO = nm;
          nm = fmaxf(mxE, s2); ZE = fmaf(ZE, ex2_(mxE-nm), ex2_(s2-nm)); mxE = nm;
          nm = fmaxf(mxO, s3); ZO = fmaf(ZO, ex2_(mxO-nm), ex2_(s3-nm)); mxO = nm;
        }
        if (h){
          float s0 = dotqk(qq, s_k + 324*20);
          srow[324] = s0;
          float nm = fmaxf(mxE, s0); ZE = fmaf(ZE, ex2_(mxE-nm), ex2_(s0-nm)); mxE = nm;
        }
        float mx = fmaxf(mxE, mxO);
        float Z  = ZE*ex2_(mxE-mx) + ZO*ex2_(mxO-mx);
        s_mxp[h*352+n] = mx;
        s_zp [h*352+n] = Z;
      }
      __syncthreads();
      if (h == 0 && n < NN){
        float mx0 = s_mxp[n], mx1 = s_mxp[352+n];
        float mx  = fmaxf(mx0, mx1);
        float Z   = s_zp[n]*ex2_(mx0-mx) + s_zp[352+n]*ex2_(mx1-mx);
        s_row[n]  = mx + lg2_(Z);
      }
      __syncthreads();

      // ---- phase 4: weighted sum from stored scores ----------------------------
      const int warp = tid >> 5, lane = tid & 31;
      const int bmh = warp & 1;
      const int bp  = (warp >> 1)*16 + (lane >> 1);
      const int bch = lane & 1;
      const int j1  = 2*bp, j2 = 2*bp + 1;

      ull xaA[8], xaB[8];
      #pragma unroll
      for (int p=0;p<8;p++){ xaA[p]=0ULL; xaB[p]=0ULL; }
      {
        const int mbase  = bmh ? 163 : 0;
        const int mcount = bmh ? 162 : 163;
        const float* sp2 = g_sc + tile*SCT + (size_t)mbase*328 + j1;
        #pragma unroll 8
        for (int i=0; i<mcount; i++){
          int m = mbase + i;
          float2 sc = *(const float2*)(sp2 + (size_t)i*328);
          float rw = s_row[m];
          float w1 = ex2_(sc.x - rw), w2 = ex2_(sc.y - rw);
          ull w12 = pack2(w1,w1), w22 = pack2(w2,w2);
          const ulonglong2* gv = (const ulonglong2*)(s_gx + m*36 + 16*bch);
          ulonglong2 gA=gv[0], gB=gv[1], gC=gv[2], gD=gv[3];
          xaA[0]=fma2(w12,gA.x,xaA[0]); xaA[1]=fma2(w12,gA.y,xaA[1]);
          xaA[2]=fma2(w12,gB.x,xaA[2]); xaA[3]=fma2(w12,gB.y,xaA[3]);
          xaA[4]=fma2(w12,gC.x,xaA[4]); xaA[5]=fma2(w12,gC.y,xaA[5]);
          xaA[6]=fma2(w12,gD.x,xaA[6]); xaA[7]=fma2(w12,gD.y,xaA[7]);
          xaB[0]=fma2(w22,gA.x,xaB[0]); xaB[1]=fma2(w22,gA.y,xaB[1]);
          xaB[2]=fma2(w22,gB.x,xaB[2]); xaB[3]=fma2(w22,gB.y,xaB[3]);
          xaB[4]=fma2(w22,gC.x,xaB[4]); xaB[5]=fma2(w22,gC.y,xaB[5]);
          xaB[6]=fma2(w22,gD.x,xaB[6]); xaB[7]=fma2(w22,gD.y,xaB[7]);
        }
      }
      __syncthreads();
      if (bmh == 0 && j1 < NN){
        ulonglong2* xp1 = (ulonglong2*)(s_xa + j1*36 + 16*bch);
        xp1[0]=make_ulonglong2(xaA[0],xaA[1]); xp1[1]=make_ulonglong2(xaA[2],xaA[3]);
        xp1[2]=make_ulonglong2(xaA[4],xaA[5]); xp1[3]=make_ulonglong2(xaA[6],xaA[7]);
        if (j2 < NN){
          ulonglong2* xp2 = (ulonglong2*)(s_xa + j2*36 + 16*bch);
          xp2[0]=make_ulonglong2(xaB[0],xaB[1]); xp2[1]=make_ulonglong2(xaB[2],xaB[3]);
          xp2[2]=make_ulonglong2(xaB[4],xaB[5]); xp2[3]=make_ulonglong2(xaB[6],xaB[7]);
        }
      }
      __syncthreads();
      if (bmh == 1 && j1 < NN){
        ull* xp1 = (ull*)(s_xa + j1*36 + 16*bch);
        #pragma unroll
        for (int p=0;p<8;p++) xp1[p] = add2(xp1[p], xaA[p]);
        if (j2 < NN){
          ull* xp2 = (ull*)(s_xa + j2*36 + 16*bch);
          #pragma unroll
          for (int p=0;p<8;p++) xp2[p] = add2(xp2[p], xaB[p]);
        }
      }
      __syncthreads();

      // ---- phase 5: mlp (packed) + residual + BN -------------------------------
      if (n < NN){
        ull o2[8];
        {
          const ulonglong2* bp2 = (const ulonglong2*)(wreg + 3616 + 16*h);
          #pragma unroll
          for (int p=0;p<4;p++){ ulonglong2 v=bp2[p]; o2[2*p]=v.x; o2[2*p+1]=v.y; }
        }
        const float4* gxv = (const float4*)(s_gx + n*36);
        const float4* xav = (const float4*)(s_xa + n*36);
        #pragma unroll 2
        for (int ci4=0; ci4<8; ci4++){
          float4 g4 = gxv[ci4];
          #pragma unroll
          for (int jj=0; jj<4; jj++){
            float xv = (jj==0)?g4.x:(jj==1)?g4.y:(jj==2)?g4.z:g4.w;
            ull xv2 = pack2(xv,xv);
            const ulonglong2* wv = (const ulonglong2*)(wreg + 1568 + (ci4*4+jj)*32 + 16*h);
            ulonglong2 wA=wv[0], wB=wv[1];
            o2[0]=fma2(xv2,wA.x,o2[0]); o2[1]=fma2(xv2,wA.y,o2[1]);
            o2[2]=fma2(xv2,wB.x,o2[2]); o2[3]=fma2(xv2,wB.y,o2[3]);
            wA=wv[2]; wB=wv[3];
            o2[4]=fma2(xv2,wA.x,o2[4]); o2[5]=fma2(xv2,wA.y,o2[5]);
            o2[6]=fma2(xv2,wB.x,o2[6]); o2[7]=fma2(xv2,wB.y,o2[7]);
          }
        }
        #pragma unroll 2
        for (int ci4=0; ci4<8; ci4++){
          float4 g4 = xav[ci4];
          #pragma unroll
          for (int jj=0; jj<4; jj++){
            float xv = (jj==0)?g4.x:(jj==1)?g4.y:(jj==2)?g4.z:g4.w;
            ull xv2 = pack2(xv,xv);
            const ulonglong2* wv = (const ulonglong2*)(wreg + 1568 + (32+ci4*4+jj)*32 + 16*h);
            ulonglong2 wA=wv[0], wB=wv[1];
            o2[0]=fma2(xv2,wA.x,o2[0]); o2[1]=fma2(xv2,wA.y,o2[1]);
            o2[2]=fma2(xv2,wB.x,o2[2]); o2[3]=fma2(xv2,wB.y,o2[3]);
            wA=wv[2]; wB=wv[3];
            o2[4]=fma2(xv2,wA.x,o2[4]); o2[5]=fma2(xv2,wA.y,o2[5]);
            o2[6]=fma2(xv2,wB.x,o2[6]); o2[7]=fma2(xv2,wB.y,o2[7]);
          }
        }
        const float* rin = Xin + base_in + dil*CNN + n;
        float* outp = Xout + base_in + n;
        #pragma unroll
        for (int p=0; p<8; p++){
          float va, vb; unpack2(o2[p], va, vb);
          int c0 = 16*h + 2*p, c1 = c0 + 1;
          float v0 = va + rin[c0*NN];
          float v1 = vb + rin[c1*NN];
          outp[c0*NN] = fmaf(v0, wreg[3648+c0], wreg[3680+c0]);
          outp[c1*NN] = fmaf(v1, wreg[3648+c1], wreg[3680+c1]);
        }
      }
    }

    // ---- publish tile completion ----------------------------------------------
    __threadfence();
    __syncthreads();
    if (tid == 0) atomicExch(&g_flag[layer*832 + b*13 + t], 1);
  }
}

// ---- host -------------------------------------------------------------------
extern "C" void kernel_launch(void* const* d_in, const int* in_sizes, int n_in,
                              void* d_out, int out_size){
  const float* x    = (const float*)d_in[0];
  const float* emb  = (const float*)d_in[1];
  const float* stW  = (const float*)d_in[2];
  const float* stb  = (const float*)d_in[3];
  const float* fW   = (const float*)d_in[4];
  const float* fb   = (const float*)d_in[5];
  const float* gW   = (const float*)d_in[6];
  const float* gb   = (const float*)d_in[7];
  const float* skW  = (const float*)d_in[8];
  const float* skb  = (const float*)d_in[9];
  const float* qW   = (const float*)d_in[10];
  const float* qb   = (const float*)d_in[11];
  const float* kW   = (const float*)d_in[12];
  const float* kb   = (const float*)d_in[13];
  const float* mW   = (const float*)d_in[14];
  const float* mb   = (const float*)d_in[15];
  const float* bng  = (const float*)d_in[16];
  const float* bnb  = (const float*)d_in[17];
  const float* bnm  = (const float*)d_in[18];
  const float* bnv  = (const float*)d_in[19];
  const float* e1W  = (const float*)d_in[20];
  const float* e1b  = (const float*)d_in[21];
  const float* e2W  = (const float*)d_in[22];
  const float* e2b  = (const float*)d_in[23];
  float* out = (float*)d_out;

  cudaFuncSetAttribute(net_kernel, cudaFuncAttributeMaxDynamicSharedMemorySize, LAYER_SMEM_BYTES);

  start_kernel<<<54627, 256>>>(x, stW, stb);

  net_kernel<<<148, NT, LAYER_SMEM_BYTES>>>(
      fW, fb, gW, gb, skW, skb, qW, qb, kW, kb, mW, mb,
      bng, bnb, bnm, bnv, emb, e1W, e1b, e2W, e2b, out);
}